// round 6
// baseline (speedup 1.0000x reference)
#include <cuda_runtime.h>
#include <cuda_bf16.h>
#include <math.h>
#include <cstdint>

#define NN 100000
#define EE 300000
#define IN_DIM 10
#define HID 384
#define TT 5
#define BN_EPS 1e-5f

#define SCAN_B 1024
#define NSCANB ((NN + SCAN_B - 1) / SCAN_B)   // 98

// Static scratch (allocation-free rule)
__device__ float          g_bufA[(size_t)NN * HID];
__device__ float          g_bufB[(size_t)NN * HID];
__device__ float          g_agg [(size_t)NN * HID];
__device__ __nv_bfloat16  g_shA [(size_t)NN * HID];
__device__ __nv_bfloat16  g_shB [(size_t)NN * HID];
__device__ int   g_deg [NN];
__device__ int   g_inc [NN];
__device__ int   g_rowptr[NN + 1];
__device__ int   g_cur [NN];
__device__ int   g_csrc[EE];
__device__ int   g_bsum[128];

// ---------------------------------------------------------------------------
// helpers
// ---------------------------------------------------------------------------
__device__ __forceinline__ uint32_t f2tf32(float f) {
    uint32_t u;
    asm("cvt.rna.tf32.f32 %0, %1;" : "=r"(u) : "f"(f));
    return u;
}

__device__ __forceinline__ void mma_tf32(float* c,
                                         uint32_t a0, uint32_t a1, uint32_t a2, uint32_t a3,
                                         uint32_t b0, uint32_t b1) {
    asm volatile("mma.sync.aligned.m16n8k8.row.col.f32.tf32.tf32.f32 "
                 "{%0,%1,%2,%3}, {%4,%5,%6,%7}, {%8,%9}, {%0,%1,%2,%3};"
                 : "+f"(c[0]), "+f"(c[1]), "+f"(c[2]), "+f"(c[3])
                 : "r"(a0), "r"(a1), "r"(a2), "r"(a3), "r"(b0), "r"(b1));
}

__device__ __forceinline__ float elu_f(float v) {
    return (v > 0.0f) ? v : (__expf(v) - 1.0f);
}

// ---------------------------------------------------------------------------
// CSR build
// ---------------------------------------------------------------------------
__global__ void k_hist(const int* __restrict__ dst, int* __restrict__ deg, int e) {
    int i = blockIdx.x * blockDim.x + threadIdx.x;
    if (i < e) atomicAdd(&deg[dst[i]], 1);
}

__global__ void k_scan_block(const int* __restrict__ deg, int* __restrict__ inc,
                             int* __restrict__ bsum, int n) {
    __shared__ int s[SCAN_B];
    int i = blockIdx.x * SCAN_B + threadIdx.x;
    s[threadIdx.x] = (i < n) ? deg[i] : 0;
    __syncthreads();
#pragma unroll
    for (int o = 1; o < SCAN_B; o <<= 1) {
        int t = (threadIdx.x >= o) ? s[threadIdx.x - o] : 0;
        __syncthreads();
        s[threadIdx.x] += t;
        __syncthreads();
    }
    if (i < n) inc[i] = s[threadIdx.x];
    if (threadIdx.x == SCAN_B - 1) bsum[blockIdx.x] = s[SCAN_B - 1];
}

__global__ void k_scan_bsum(int* __restrict__ bsum, int nb) {
    __shared__ int s[128];
    if (threadIdx.x < nb) s[threadIdx.x] = bsum[threadIdx.x];
    __syncthreads();
    if (threadIdx.x == 0) {
        int run = 0;
        for (int i = 0; i < nb; i++) { run += s[i]; s[i] = run; }
    }
    __syncthreads();
    if (threadIdx.x < nb) bsum[threadIdx.x] = s[threadIdx.x];
}

__global__ void k_csr_fin(const int* __restrict__ deg, const int* __restrict__ inc,
                          const int* __restrict__ bsum,
                          int* __restrict__ rowptr, int* __restrict__ cur, int n) {
    int i = blockIdx.x * blockDim.x + threadIdx.x;
    if (i >= n) return;
    int b = i / SCAN_B;
    int total = inc[i] + (b > 0 ? bsum[b - 1] : 0);
    rowptr[i + 1] = total;
    cur[i] = total - deg[i];
    if (i == 0) rowptr[0] = 0;
}

__global__ void k_fill(const int* __restrict__ src, const int* __restrict__ dst,
                       int* __restrict__ cur, int* __restrict__ csrc, int e) {
    int i = blockIdx.x * blockDim.x + threadIdx.x;
    if (i >= e) return;
    int pos = atomicAdd(&cur[dst[i]], 1);
    csrc[pos] = src[i];
}

// ---------------------------------------------------------------------------
// CSR mean-gather, width 384, bf16 source (L2-resident), fp32 accumulate
// ---------------------------------------------------------------------------
__global__ void k_gather384(const int* __restrict__ rowptr, const int* __restrict__ csrc,
                            const __nv_bfloat16* __restrict__ hs, float* __restrict__ agg,
                            int n) {
    int node = (blockIdx.x * blockDim.x + threadIdx.x) >> 5;
    int lane = threadIdx.x & 31;
    if (node >= n) return;
    int beg = rowptr[node], end = rowptr[node + 1];
    float a[12];
#pragma unroll
    for (int i = 0; i < 12; i++) a[i] = 0.0f;
    for (int e = beg; e < end; e++) {
        const uint2* p = (const uint2*)(hs + (size_t)csrc[e] * HID) + lane;
        uint2 u0 = p[0], u1 = p[32], u2 = p[64];
        float2 f;
        f = __bfloat1622float2(*(__nv_bfloat162*)&u0.x); a[0] += f.x; a[1] += f.y;
        f = __bfloat1622float2(*(__nv_bfloat162*)&u0.y); a[2] += f.x; a[3] += f.y;
        f = __bfloat1622float2(*(__nv_bfloat162*)&u1.x); a[4] += f.x; a[5] += f.y;
        f = __bfloat1622float2(*(__nv_bfloat162*)&u1.y); a[6] += f.x; a[7] += f.y;
        f = __bfloat1622float2(*(__nv_bfloat162*)&u2.x); a[8] += f.x; a[9] += f.y;
        f = __bfloat1622float2(*(__nv_bfloat162*)&u2.y); a[10] += f.x; a[11] += f.y;
    }
    float iv = 1.0f / fmaxf((float)(end - beg), 1.0f);
    float4* o = (float4*)(agg + (size_t)node * HID) + lane;
    o[0]  = make_float4(a[0] * iv, a[1] * iv, a[2] * iv, a[3] * iv);
    o[32] = make_float4(a[4] * iv, a[5] * iv, a[6] * iv, a[7] * iv);
    o[64] = make_float4(a[8] * iv, a[9] * iv, a[10] * iv, a[11] * iv);
}

// width 10: thread per (node, feature), fp32 source
__global__ void k_gather10(const int* __restrict__ rowptr, const int* __restrict__ csrc,
                           const float* __restrict__ x, float* __restrict__ agg, int n) {
    int idx = blockIdx.x * blockDim.x + threadIdx.x;
    if (idx >= n * IN_DIM) return;
    int node = idx / IN_DIM, f = idx % IN_DIM;
    int beg = rowptr[node], end = rowptr[node + 1];
    float a = 0.0f;
    for (int e = beg; e < end; e++)
        a += x[(size_t)csrc[e] * IN_DIM + f];
    agg[idx] = a / fmaxf((float)(end - beg), 1.0f);
}

// ---------------------------------------------------------------------------
// Layer 0 SAGE: K=10, 16 rows/block, 384 threads; writes fp32 + bf16 shadow
// ---------------------------------------------------------------------------
__global__ void k_layer0(const float* __restrict__ agg, const float* __restrict__ x,
                         const float* __restrict__ Wl, const float* __restrict__ bl,
                         const float* __restrict__ Wr,
                         const float* __restrict__ bng, const float* __restrict__ bnb,
                         const float* __restrict__ bnm, const float* __restrict__ bnv,
                         float* __restrict__ out, __nv_bfloat16* __restrict__ hs, int n) {
    __shared__ float sA[16][IN_DIM];
    __shared__ float sX[16][IN_DIM];
    __shared__ float red[16];
    int t = threadIdx.x;
    int row0 = blockIdx.x * 16;

    if (t < 160) {
        int r = t / IN_DIM, k = t % IN_DIM;
        int row = row0 + r;
        sA[r][k] = (row < n) ? agg[(size_t)row * IN_DIM + k] : 0.0f;
    } else if (t < 320) {
        int q = t - 160;
        int r = q / IN_DIM, k = q % IN_DIM;
        int row = row0 + r;
        sX[r][k] = (row < n) ? x[(size_t)row * IN_DIM + k] : 0.0f;
    } else if (t < 336) {
        red[t - 320] = 0.0f;
    }
    __syncthreads();

    int j = t;
    float wl[IN_DIM], wr[IN_DIM];
#pragma unroll
    for (int k = 0; k < IN_DIM; k++) {
        wl[k] = Wl[j * IN_DIM + k];
        wr[k] = Wr[j * IN_DIM + k];
    }
    float bb = bl[j];

    float v[16];
#pragma unroll
    for (int r = 0; r < 16; r++) {
        float s = bb;
#pragma unroll
        for (int k = 0; k < IN_DIM; k++)
            s += sA[r][k] * wl[k] + sX[r][k] * wr[k];
        v[r] = s;
    }

    int lane = t & 31;
#pragma unroll
    for (int r = 0; r < 16; r++) {
        float p = v[r] * v[r];
#pragma unroll
        for (int o = 16; o > 0; o >>= 1) p += __shfl_xor_sync(0xFFFFFFFFu, p, o);
        if (lane == 0) atomicAdd(&red[r], p);
    }
    __syncthreads();

    float gm = bng[j], gb = bnb[j], mm = bnm[j], vv = bnv[j];
    float bscale = rsqrtf(vv + BN_EPS) * gm;
#pragma unroll
    for (int r = 0; r < 16; r++) {
        int row = row0 + r;
        if (row >= n) continue;
        float sc = 1.0f / fmaxf(sqrtf(red[r]), 1e-12f);
        float val = elu_f((v[r] * sc - mm) * bscale + gb);
        out[(size_t)row * HID + j] = val;
        hs [(size_t)row * HID + j] = __float2bfloat16(val);
    }
}

// ---------------------------------------------------------------------------
// tf32 mma.sync fused GEMM, paired-k SMEM layout, double-buffered (1 sync/iter)
//   C[64, 384] = A1 * W1^T (+ A2 * W2^T) + bias
//   epi 0: L2-normalize row, BN, ELU (+ bf16 shadow)
//   epi 1: BN, ReLU
//   epi 2: BN, ReLU, then out3 = h @ Wp2^T + bp2  (writes [N,3] only)
// ---------------------------------------------------------------------------
#define ASTR 18
// dynamic smem layout (floats)
#define OFF_WS   0
#define WS_BUF   (384 * ASTR)             // 6912
#define OFF_AS   (2 * WS_BUF)             // 13824
#define AS_BUF   (64 * ASTR)              // 1152
#define OFF_SB   (OFF_AS + 2 * AS_BUF)    // 16128
#define OFF_S2   (OFF_SB + HID)
#define OFF_AD   (OFF_S2 + HID)
#define OFF_WP   (OFF_AD + HID)           // 17280 (3*384)
#define OFF_RED  (OFF_WP + 3 * HID)       // 18432 (64)
#define OFF_REDF (OFF_RED + 64)           // 18496 (192)
#define SMEM_FLOATS (OFF_REDF + 192)      // 18688
#define SMEM_BYTES  (SMEM_FLOATS * 4)     // 74752

// position of k (0..15) in paired layout: (k,k+4) adjacent
__device__ __forceinline__ int kpos(int k) {
    return ((k >> 3) << 3) + ((k & 3) << 1) + ((k >> 2) & 1);
}

__global__ void __launch_bounds__(512)
k_mma(const float* __restrict__ A1, const float* __restrict__ W1,
      const float* __restrict__ bias,
      const float* __restrict__ A2, const float* __restrict__ W2,
      const float* __restrict__ bng, const float* __restrict__ bnb,
      const float* __restrict__ bnm, const float* __restrict__ bnv,
      float* __restrict__ out, int nrows, int epi,
      __nv_bfloat16* __restrict__ hs,
      const float* __restrict__ Wp2, const float* __restrict__ bp2) {
    extern __shared__ float sm[];
    float* Ws  = sm + OFF_WS;
    float* As  = sm + OFF_AS;
    float* sSB = sm + OFF_SB;
    float* sS2 = sm + OFF_S2;
    float* sAD = sm + OFF_AD;
    float* sWp = sm + OFF_WP;
    float* red = sm + OFF_RED;
    float* redF= sm + OFF_REDF;

    const int tid  = threadIdx.x;
    const int lane = tid & 31;
    const int wid  = tid >> 5;
    const int rw   = wid & 1;
    const int cw   = wid >> 1;
    const int g    = lane >> 2;
    const int t4   = lane & 3;
    const int warpRow = rw * 32;
    const int cb   = cw * 48;
    const int rb   = blockIdx.x * 64;

    for (int c = tid; c < HID; c += 512) {
        float s2 = rsqrtf(bnv[c] + BN_EPS) * bng[c];
        sSB[c] = bias[c];
        sS2[c] = s2;
        sAD[c] = bnb[c] - bnm[c] * s2;
    }
    if (tid < 64) red[tid] = 0.0f;
    if (tid < 192) redF[tid] = 0.0f;
    if (epi == 2)
        for (int c = tid; c < 3 * HID; c += 512) sWp[c] = Wp2[c];
    __syncthreads();

    // loader indices
    const int ar = tid >> 2, aq = tid & 3;
    const int aPosBase = ((aq >= 2) ? 8 : 0) + (aq & 1);
    int wr_[3], wPosBase[3];
#pragma unroll
    for (int i = 0; i < 3; i++) {
        int idx = tid + i * 512;
        wr_[i] = idx >> 2;
        int wq = idx & 3;
        wPosBase[i] = ((wq >= 2) ? 8 : 0) + (wq & 1);
    }

    const int npass = (A2 == nullptr) ? 1 : 2;
    const int S = 24 * npass;

    float acc[2][6][4];
#pragma unroll
    for (int mt = 0; mt < 2; mt++)
#pragma unroll
        for (int nt = 0; nt < 6; nt++)
#pragma unroll
            for (int q = 0; q < 4; q++) acc[mt][nt][q] = 0.0f;

    float4 avP = make_float4(0.f, 0.f, 0.f, 0.f);
    float4 wvP[3];

    // prologue fetch it=0
    {
        if (tid < 256) {
            int row = rb + ar;
            if (row < nrows)
                avP = *(const float4*)(A1 + (size_t)row * HID + aq * 4);
        }
#pragma unroll
        for (int i = 0; i < 3; i++)
            wvP[i] = *(const float4*)(W1 + (size_t)wr_[i] * HID + (aq * 0) + ((tid + i * 512) & 3) * 4);
    }

    for (int it = 0; it < S; it++) {
        const int buf = it & 1;
        float* Ab = As + buf * AS_BUF;
        float* Wb = Ws + buf * WS_BUF;

        // stage regs -> SMEM (paired-k positions, tf32-rounded)
        if (tid < 256) {
            float* p = Ab + ar * ASTR + aPosBase;
            ((uint32_t*)p)[0] = f2tf32(avP.x);
            ((uint32_t*)p)[2] = f2tf32(avP.y);
            ((uint32_t*)p)[4] = f2tf32(avP.z);
            ((uint32_t*)p)[6] = f2tf32(avP.w);
        }
#pragma unroll
        for (int i = 0; i < 3; i++) {
            float* p = Wb + wr_[i] * ASTR + wPosBase[i];
            ((uint32_t*)p)[0] = f2tf32(wvP[i].x);
            ((uint32_t*)p)[2] = f2tf32(wvP[i].y);
            ((uint32_t*)p)[4] = f2tf32(wvP[i].z);
            ((uint32_t*)p)[6] = f2tf32(wvP[i].w);
        }
        __syncthreads();

        // prefetch next chunk
        if (it + 1 < S) {
            const int itn = it + 1;
            const int pass = itn / 24;
            const int k0 = (itn % 24) * 16;
            const float* A = pass ? A2 : A1;
            const float* W = pass ? W2 : W1;
            if (tid < 256) {
                int row = rb + ar;
                avP = make_float4(0.f, 0.f, 0.f, 0.f);
                if (row < nrows)
                    avP = *(const float4*)(A + (size_t)row * HID + k0 + aq * 4);
            }
#pragma unroll
            for (int i = 0; i < 3; i++) {
                int wq = (tid + i * 512) & 3;
                wvP[i] = *(const float4*)(W + (size_t)wr_[i] * HID + k0 + wq * 4);
            }
        }

        // compute: 2 k8 steps, LDS.64 fragment loads
#pragma unroll
        for (int ks = 0; ks < 2; ks++) {
            const int kb = ks * 8 + t4 * 2;
            float2 af[2][2];
#pragma unroll
            for (int mt = 0; mt < 2; mt++) {
                int r0 = warpRow + mt * 16 + g;
                af[mt][0] = *(float2*)&Ab[r0 * ASTR + kb];
                af[mt][1] = *(float2*)&Ab[(r0 + 8) * ASTR + kb];
            }
#pragma unroll
            for (int nt = 0; nt < 6; nt++) {
                int n0 = cb + nt * 8 + g;
                float2 bf = *(float2*)&Wb[n0 * ASTR + kb];
                uint32_t b0 = __float_as_uint(bf.x), b1 = __float_as_uint(bf.y);
#pragma unroll
                for (int mt = 0; mt < 2; mt++)
                    mma_tf32(acc[mt][nt],
                             __float_as_uint(af[mt][0].x), __float_as_uint(af[mt][1].x),
                             __float_as_uint(af[mt][0].y), __float_as_uint(af[mt][1].y),
                             b0, b1);
            }
        }
        // no second sync: double buffer
    }

    // ---- epilogue ----
#pragma unroll
    for (int nt = 0; nt < 6; nt++) {
        int col = cb + nt * 8 + 2 * t4;
        float b0 = sSB[col], b1 = sSB[col + 1];
#pragma unroll
        for (int mt = 0; mt < 2; mt++) {
            acc[mt][nt][0] += b0; acc[mt][nt][1] += b1;
            acc[mt][nt][2] += b0; acc[mt][nt][3] += b1;
        }
    }

    float sc0[2] = {1.0f, 1.0f}, sc1[2] = {1.0f, 1.0f};
    if (epi == 0) {
#pragma unroll
        for (int mt = 0; mt < 2; mt++) {
            float s0 = 0.0f, s1 = 0.0f;
#pragma unroll
            for (int nt = 0; nt < 6; nt++) {
                s0 = fmaf(acc[mt][nt][0], acc[mt][nt][0], s0);
                s0 = fmaf(acc[mt][nt][1], acc[mt][nt][1], s0);
                s1 = fmaf(acc[mt][nt][2], acc[mt][nt][2], s1);
                s1 = fmaf(acc[mt][nt][3], acc[mt][nt][3], s1);
            }
            s0 += __shfl_xor_sync(0xFFFFFFFFu, s0, 1);
            s0 += __shfl_xor_sync(0xFFFFFFFFu, s0, 2);
            s1 += __shfl_xor_sync(0xFFFFFFFFu, s1, 1);
            s1 += __shfl_xor_sync(0xFFFFFFFFu, s1, 2);
            if (t4 == 0) {
                atomicAdd(&red[warpRow + mt * 16 + g], s0);
                atomicAdd(&red[warpRow + mt * 16 + g + 8], s1);
            }
        }
        __syncthreads();
#pragma unroll
        for (int mt = 0; mt < 2; mt++) {
            sc0[mt] = 1.0f / fmaxf(sqrtf(red[warpRow + mt * 16 + g]), 1e-12f);
            sc1[mt] = 1.0f / fmaxf(sqrtf(red[warpRow + mt * 16 + g + 8]), 1e-12f);
        }
    }

    if (epi == 2) {
        // BN + ReLU, then partial dot with Wp2 (3 outputs), reduce into redF
        float p0[2][3];   // [rowslot][o] for row0(this g) ; rowslot over mt
        float p1[2][3];
#pragma unroll
        for (int mt = 0; mt < 2; mt++)
#pragma unroll
            for (int o = 0; o < 3; o++) { p0[mt][o] = 0.0f; p1[mt][o] = 0.0f; }

#pragma unroll
        for (int mt = 0; mt < 2; mt++) {
#pragma unroll
            for (int nt = 0; nt < 6; nt++) {
                int col = cb + nt * 8 + 2 * t4;
                float m0 = sS2[col], m1 = sS2[col + 1];
                float d0 = sAD[col], d1 = sAD[col + 1];
                float x0 = fmaxf(acc[mt][nt][0] * m0 + d0, 0.0f);
                float x1 = fmaxf(acc[mt][nt][1] * m1 + d1, 0.0f);
                float x2 = fmaxf(acc[mt][nt][2] * m0 + d0, 0.0f);
                float x3 = fmaxf(acc[mt][nt][3] * m1 + d1, 0.0f);
#pragma unroll
                for (int o = 0; o < 3; o++) {
                    float w0 = sWp[o * HID + col], w1 = sWp[o * HID + col + 1];
                    p0[mt][o] = fmaf(x0, w0, fmaf(x1, w1, p0[mt][o]));
                    p1[mt][o] = fmaf(x2, w0, fmaf(x3, w1, p1[mt][o]));
                }
            }
        }
        // reduce over t4 lanes, then over the 8 col-warps via smem atomics
#pragma unroll
        for (int mt = 0; mt < 2; mt++)
#pragma unroll
            for (int o = 0; o < 3; o++) {
                float v0 = p0[mt][o], v1 = p1[mt][o];
                v0 += __shfl_xor_sync(0xFFFFFFFFu, v0, 1);
                v0 += __shfl_xor_sync(0xFFFFFFFFu, v0, 2);
                v1 += __shfl_xor_sync(0xFFFFFFFFu, v1, 1);
                v1 += __shfl_xor_sync(0xFFFFFFFFu, v1, 2);
                if (t4 == 0) {
                    atomicAdd(&redF[(warpRow + mt * 16 + g) * 3 + o], v0);
                    atomicAdd(&redF[(warpRow + mt * 16 + g + 8) * 3 + o], v1);
                }
            }
        __syncthreads();
        if (tid < 64) {
            int row = rb + tid;
            if (row < nrows) {
                out[(size_t)row * 3 + 0] = redF[tid * 3 + 0] + bp2[0];
                out[(size_t)row * 3 + 1] = redF[tid * 3 + 1] + bp2[1];
                out[(size_t)row * 3 + 2] = redF[tid * 3 + 2] + bp2[2];
            }
        }
        return;
    }

#pragma unroll
    for (int mt = 0; mt < 2; mt++) {
        int row0 = rb + warpRow + mt * 16 + g;
        int row1 = row0 + 8;
        bool v0r = (row0 < nrows), v1r = (row1 < nrows);
#pragma unroll
        for (int nt = 0; nt < 6; nt++) {
            int col = cb + nt * 8 + 2 * t4;
            float m0 = sS2[col], m1 = sS2[col + 1];
            float d0 = sAD[col], d1 = sAD[col + 1];
            float x0 = acc[mt][nt][0] * sc0[mt] * m0 + d0;
            float x1 = acc[mt][nt][1] * sc0[mt] * m1 + d1;
            float x2 = acc[mt][nt][2] * sc1[mt] * m0 + d0;
            float x3 = acc[mt][nt][3] * sc1[mt] * m1 + d1;
            if (epi == 0) {
                x0 = elu_f(x0); x1 = elu_f(x1);
                x2 = elu_f(x2); x3 = elu_f(x3);
            } else {
                x0 = fmaxf(x0, 0.0f); x1 = fmaxf(x1, 0.0f);
                x2 = fmaxf(x2, 0.0f); x3 = fmaxf(x3, 0.0f);
            }
            if (v0r) {
                *(float2*)(out + (size_t)row0 * HID + col) = make_float2(x0, x1);
                if (hs) *(__nv_bfloat162*)(hs + (size_t)row0 * HID + col) =
                            __floats2bfloat162_rn(x0, x1);
            }
            if (v1r) {
                *(float2*)(out + (size_t)row1 * HID + col) = make_float2(x2, x3);
                if (hs) *(__nv_bfloat162*)(hs + (size_t)row1 * HID + col) =
                            __floats2bfloat162_rn(x2, x3);
            }
        }
    }
}

// ---------------------------------------------------------------------------
extern "C" void kernel_launch(void* const* d_in, const int* in_sizes, int n_in,
                              void* d_out, int out_size) {
    const float* x    = (const float*)d_in[0];
    const int*   ei   = (const int*)  d_in[1];
    const float* Wl0  = (const float*)d_in[2];
    const float* bl0  = (const float*)d_in[3];
    const float* Wr0  = (const float*)d_in[4];
    const float* Wl   = (const float*)d_in[5];
    const float* bl   = (const float*)d_in[6];
    const float* Wr   = (const float*)d_in[7];
    const float* bng  = (const float*)d_in[8];
    const float* bnb  = (const float*)d_in[9];
    const float* bnm  = (const float*)d_in[10];
    const float* bnv  = (const float*)d_in[11];
    const float* Wp0  = (const float*)d_in[12];
    const float* bp0  = (const float*)d_in[13];
    const float* Wp1  = (const float*)d_in[14];
    const float* bp1  = (const float*)d_in[15];
    const float* Wp2  = (const float*)d_in[16];
    const float* bp2  = (const float*)d_in[17];
    const float* pg   = (const float*)d_in[18];
    const float* pb   = (const float*)d_in[19];
    const float* pm   = (const float*)d_in[20];
    const float* pv   = (const float*)d_in[21];

    const int* src = ei;
    const int* dst = ei + EE;

    float *hA, *hB, *agg;
    __nv_bfloat16 *shA, *shB;
    int *deg, *inc, *rowptr, *cur, *csrc, *bsum;
    cudaGetSymbolAddress((void**)&hA,     g_bufA);
    cudaGetSymbolAddress((void**)&hB,     g_bufB);
    cudaGetSymbolAddress((void**)&agg,    g_agg);
    cudaGetSymbolAddress((void**)&shA,    g_shA);
    cudaGetSymbolAddress((void**)&shB,    g_shB);
    cudaGetSymbolAddress((void**)&deg,    g_deg);
    cudaGetSymbolAddress((void**)&inc,    g_inc);
    cudaGetSymbolAddress((void**)&rowptr, g_rowptr);
    cudaGetSymbolAddress((void**)&cur,    g_cur);
    cudaGetSymbolAddress((void**)&csrc,   g_csrc);
    cudaGetSymbolAddress((void**)&bsum,   g_bsum);

    cudaFuncSetAttribute(k_mma, cudaFuncAttributeMaxDynamicSharedMemorySize, SMEM_BYTES);

    // ---- CSR build ----
    cudaMemsetAsync(deg, 0, NN * sizeof(int));
    k_hist<<<(EE + 255) / 256, 256>>>(dst, deg, EE);
    k_scan_block<<<NSCANB, SCAN_B>>>(deg, inc, bsum, NN);
    k_scan_bsum<<<1, 128>>>(bsum, NSCANB);
    k_csr_fin<<<(NN + 255) / 256, 256>>>(deg, inc, bsum, rowptr, cur, NN);
    k_fill<<<(EE + 255) / 256, 256>>>(src, dst, cur, csrc, EE);

    // ---- layer 0 (K=10) ----
    k_gather10<<<(NN * IN_DIM + 255) / 256, 256>>>(rowptr, csrc, x, agg, NN);
    k_layer0<<<(NN + 15) / 16, 384>>>(agg, x, Wl0, bl0, Wr0,
                                      bng, bnb, bnm, bnv, hA, shA, NN);

    // ---- layers 1..4: bf16 gather + dual tf32 mma GEMM ----
    const int gblocks = (NN + 63) / 64;
    for (int t = 1; t < TT; t++) {
        k_gather384<<<(NN * 32 + 255) / 256, 256>>>(rowptr, csrc, shA, agg, NN);
        k_mma<<<gblocks, 512, SMEM_BYTES>>>(
            agg, Wl + (size_t)(t - 1) * HID * HID, bl + (t - 1) * HID,
            hA,  Wr + (size_t)(t - 1) * HID * HID,
            bng + t * HID, bnb + t * HID, bnm + t * HID, bnv + t * HID,
            hB, NN, 0, (t < TT - 1) ? shB : nullptr, nullptr, nullptr);
        float* tf = hA; hA = hB; hB = tf;
        __nv_bfloat16* ts = shA; shA = shB; shB = ts;
    }

    // ---- projection MLP (final [384->3] fused into second GEMM) ----
    k_mma<<<gblocks, 512, SMEM_BYTES>>>(hA, Wp0, bp0, nullptr, nullptr,
                                        pg, pb, pm, pv, hB, NN, 1,
                                        nullptr, nullptr, nullptr);
    k_mma<<<gblocks, 512, SMEM_BYTES>>>(hB, Wp1, bp1, nullptr, nullptr,
                                        pg + HID, pb + HID, pm + HID, pv + HID,
                                        (float*)d_out, NN, 2,
                                        nullptr, Wp2, bp2);

    (void)in_sizes; (void)n_in; (void)out_size;
}

// round 7
// speedup vs baseline: 1.1172x; 1.1172x over previous
#include <cuda_runtime.h>
#include <cuda_bf16.h>
#include <math.h>
#include <cstdint>

#define NN 100000
#define EE 300000
#define IN_DIM 10
#define HID 384
#define TT 5
#define BN_EPS 1e-5f

#define SCAN_B 1024
#define NSCANB ((NN + SCAN_B - 1) / SCAN_B)   // 98

// Static scratch (allocation-free rule)
__device__ float          g_bufA[(size_t)NN * HID];
__device__ float          g_bufB[(size_t)NN * HID];
__device__ float          g_agg [(size_t)NN * HID];
__device__ __nv_bfloat16  g_shA [(size_t)NN * HID];
__device__ __nv_bfloat16  g_shB [(size_t)NN * HID];
__device__ int   g_deg [NN];
__device__ int   g_inc [NN];
__device__ int   g_rowptr[NN + 1];
__device__ int   g_cur [NN];
__device__ int   g_csrc[EE];
__device__ int   g_bsum[128];

// ---------------------------------------------------------------------------
// helpers
// ---------------------------------------------------------------------------
__device__ __forceinline__ uint32_t f2tf32(float f) {
    uint32_t u;
    asm("cvt.rna.tf32.f32 %0, %1;" : "=r"(u) : "f"(f));
    return u;
}

__device__ __forceinline__ void mma_tf32(float* c,
                                         uint32_t a0, uint32_t a1, uint32_t a2, uint32_t a3,
                                         uint32_t b0, uint32_t b1) {
    asm volatile("mma.sync.aligned.m16n8k8.row.col.f32.tf32.tf32.f32 "
                 "{%0,%1,%2,%3}, {%4,%5,%6,%7}, {%8,%9}, {%0,%1,%2,%3};"
                 : "+f"(c[0]), "+f"(c[1]), "+f"(c[2]), "+f"(c[3])
                 : "r"(a0), "r"(a1), "r"(a2), "r"(a3), "r"(b0), "r"(b1));
}

__device__ __forceinline__ float elu_f(float v) {
    return (v > 0.0f) ? v : (__expf(v) - 1.0f);
}

// ---------------------------------------------------------------------------
// CSR build
// ---------------------------------------------------------------------------
__global__ void k_hist(const int* __restrict__ dst, int* __restrict__ deg, int e) {
    int i = blockIdx.x * blockDim.x + threadIdx.x;
    if (i < e) atomicAdd(&deg[dst[i]], 1);
}

__global__ void k_scan_block(const int* __restrict__ deg, int* __restrict__ inc,
                             int* __restrict__ bsum, int n) {
    __shared__ int s[SCAN_B];
    int i = blockIdx.x * SCAN_B + threadIdx.x;
    s[threadIdx.x] = (i < n) ? deg[i] : 0;
    __syncthreads();
#pragma unroll
    for (int o = 1; o < SCAN_B; o <<= 1) {
        int t = (threadIdx.x >= o) ? s[threadIdx.x - o] : 0;
        __syncthreads();
        s[threadIdx.x] += t;
        __syncthreads();
    }
    if (i < n) inc[i] = s[threadIdx.x];
    if (threadIdx.x == SCAN_B - 1) bsum[blockIdx.x] = s[SCAN_B - 1];
}

__global__ void k_scan_bsum(int* __restrict__ bsum, int nb) {
    __shared__ int s[128];
    if (threadIdx.x < nb) s[threadIdx.x] = bsum[threadIdx.x];
    __syncthreads();
    if (threadIdx.x == 0) {
        int run = 0;
        for (int i = 0; i < nb; i++) { run += s[i]; s[i] = run; }
    }
    __syncthreads();
    if (threadIdx.x < nb) bsum[threadIdx.x] = s[threadIdx.x];
}

__global__ void k_csr_fin(const int* __restrict__ deg, const int* __restrict__ inc,
                          const int* __restrict__ bsum,
                          int* __restrict__ rowptr, int* __restrict__ cur, int n) {
    int i = blockIdx.x * blockDim.x + threadIdx.x;
    if (i >= n) return;
    int b = i / SCAN_B;
    int total = inc[i] + (b > 0 ? bsum[b - 1] : 0);
    rowptr[i + 1] = total;
    cur[i] = total - deg[i];
    if (i == 0) rowptr[0] = 0;
}

__global__ void k_fill(const int* __restrict__ src, const int* __restrict__ dst,
                       int* __restrict__ cur, int* __restrict__ csrc, int e) {
    int i = blockIdx.x * blockDim.x + threadIdx.x;
    if (i >= e) return;
    int pos = atomicAdd(&cur[dst[i]], 1);
    csrc[pos] = src[i];
}

// ---------------------------------------------------------------------------
// CSR mean-gather, width 384, bf16 source, fp32 accumulate.
// Edge loop unrolled x2 with independent accumulators (double the MLP).
// ---------------------------------------------------------------------------
__global__ void k_gather384(const int* __restrict__ rowptr, const int* __restrict__ csrc,
                            const __nv_bfloat16* __restrict__ hs, float* __restrict__ agg,
                            int n) {
    int node = (blockIdx.x * blockDim.x + threadIdx.x) >> 5;
    int lane = threadIdx.x & 31;
    if (node >= n) return;
    int beg = rowptr[node], end = rowptr[node + 1];
    float a[12], b[12];
#pragma unroll
    for (int i = 0; i < 12; i++) { a[i] = 0.0f; b[i] = 0.0f; }

    int e = beg;
    for (; e + 1 < end; e += 2) {
        int s0 = csrc[e], s1 = csrc[e + 1];
        const uint2* p0 = (const uint2*)(hs + (size_t)s0 * HID) + lane;
        const uint2* p1 = (const uint2*)(hs + (size_t)s1 * HID) + lane;
        uint2 u0 = p0[0], u1 = p0[32], u2 = p0[64];
        uint2 w0 = p1[0], w1 = p1[32], w2 = p1[64];
        float2 f;
        f = __bfloat1622float2(*(__nv_bfloat162*)&u0.x); a[0] += f.x; a[1] += f.y;
        f = __bfloat1622float2(*(__nv_bfloat162*)&u0.y); a[2] += f.x; a[3] += f.y;
        f = __bfloat1622float2(*(__nv_bfloat162*)&u1.x); a[4] += f.x; a[5] += f.y;
        f = __bfloat1622float2(*(__nv_bfloat162*)&u1.y); a[6] += f.x; a[7] += f.y;
        f = __bfloat1622float2(*(__nv_bfloat162*)&u2.x); a[8] += f.x; a[9] += f.y;
        f = __bfloat1622float2(*(__nv_bfloat162*)&u2.y); a[10] += f.x; a[11] += f.y;
        f = __bfloat1622float2(*(__nv_bfloat162*)&w0.x); b[0] += f.x; b[1] += f.y;
        f = __bfloat1622float2(*(__nv_bfloat162*)&w0.y); b[2] += f.x; b[3] += f.y;
        f = __bfloat1622float2(*(__nv_bfloat162*)&w1.x); b[4] += f.x; b[5] += f.y;
        f = __bfloat1622float2(*(__nv_bfloat162*)&w1.y); b[6] += f.x; b[7] += f.y;
        f = __bfloat1622float2(*(__nv_bfloat162*)&w2.x); b[8] += f.x; b[9] += f.y;
        f = __bfloat1622float2(*(__nv_bfloat162*)&w2.y); b[10] += f.x; b[11] += f.y;
    }
    if (e < end) {
        const uint2* p0 = (const uint2*)(hs + (size_t)csrc[e] * HID) + lane;
        uint2 u0 = p0[0], u1 = p0[32], u2 = p0[64];
        float2 f;
        f = __bfloat1622float2(*(__nv_bfloat162*)&u0.x); a[0] += f.x; a[1] += f.y;
        f = __bfloat1622float2(*(__nv_bfloat162*)&u0.y); a[2] += f.x; a[3] += f.y;
        f = __bfloat1622float2(*(__nv_bfloat162*)&u1.x); a[4] += f.x; a[5] += f.y;
        f = __bfloat1622float2(*(__nv_bfloat162*)&u1.y); a[6] += f.x; a[7] += f.y;
        f = __bfloat1622float2(*(__nv_bfloat162*)&u2.x); a[8] += f.x; a[9] += f.y;
        f = __bfloat1622float2(*(__nv_bfloat162*)&u2.y); a[10] += f.x; a[11] += f.y;
    }

    float iv = 1.0f / fmaxf((float)(end - beg), 1.0f);
    float4* o = (float4*)(agg + (size_t)node * HID) + lane;
    o[0]  = make_float4((a[0]+b[0])*iv, (a[1]+b[1])*iv, (a[2]+b[2])*iv, (a[3]+b[3])*iv);
    o[32] = make_float4((a[4]+b[4])*iv, (a[5]+b[5])*iv, (a[6]+b[6])*iv, (a[7]+b[7])*iv);
    o[64] = make_float4((a[8]+b[8])*iv, (a[9]+b[9])*iv, (a[10]+b[10])*iv, (a[11]+b[11])*iv);
}

// width 10: thread per (node, feature), fp32 source
__global__ void k_gather10(const int* __restrict__ rowptr, const int* __restrict__ csrc,
                           const float* __restrict__ x, float* __restrict__ agg, int n) {
    int idx = blockIdx.x * blockDim.x + threadIdx.x;
    if (idx >= n * IN_DIM) return;
    int node = idx / IN_DIM, f = idx % IN_DIM;
    int beg = rowptr[node], end = rowptr[node + 1];
    float a = 0.0f;
    for (int e = beg; e < end; e++)
        a += x[(size_t)csrc[e] * IN_DIM + f];
    agg[idx] = a / fmaxf((float)(end - beg), 1.0f);
}

// ---------------------------------------------------------------------------
// Layer 0 SAGE: K=10, 16 rows/block, 384 threads; writes fp32 + bf16 shadow
// ---------------------------------------------------------------------------
__global__ void k_layer0(const float* __restrict__ agg, const float* __restrict__ x,
                         const float* __restrict__ Wl, const float* __restrict__ bl,
                         const float* __restrict__ Wr,
                         const float* __restrict__ bng, const float* __restrict__ bnb,
                         const float* __restrict__ bnm, const float* __restrict__ bnv,
                         float* __restrict__ out, __nv_bfloat16* __restrict__ hs, int n) {
    __shared__ float sA[16][IN_DIM];
    __shared__ float sX[16][IN_DIM];
    __shared__ float red[16];
    int t = threadIdx.x;
    int row0 = blockIdx.x * 16;

    if (t < 160) {
        int r = t / IN_DIM, k = t % IN_DIM;
        int row = row0 + r;
        sA[r][k] = (row < n) ? agg[(size_t)row * IN_DIM + k] : 0.0f;
    } else if (t < 320) {
        int q = t - 160;
        int r = q / IN_DIM, k = q % IN_DIM;
        int row = row0 + r;
        sX[r][k] = (row < n) ? x[(size_t)row * IN_DIM + k] : 0.0f;
    } else if (t < 336) {
        red[t - 320] = 0.0f;
    }
    __syncthreads();

    int j = t;
    float wl[IN_DIM], wr[IN_DIM];
#pragma unroll
    for (int k = 0; k < IN_DIM; k++) {
        wl[k] = Wl[j * IN_DIM + k];
        wr[k] = Wr[j * IN_DIM + k];
    }
    float bb = bl[j];

    float v[16];
#pragma unroll
    for (int r = 0; r < 16; r++) {
        float s = bb;
#pragma unroll
        for (int k = 0; k < IN_DIM; k++)
            s += sA[r][k] * wl[k] + sX[r][k] * wr[k];
        v[r] = s;
    }

    int lane = t & 31;
#pragma unroll
    for (int r = 0; r < 16; r++) {
        float p = v[r] * v[r];
#pragma unroll
        for (int o = 16; o > 0; o >>= 1) p += __shfl_xor_sync(0xFFFFFFFFu, p, o);
        if (lane == 0) atomicAdd(&red[r], p);
    }
    __syncthreads();

    float gm = bng[j], gb = bnb[j], mm = bnm[j], vv = bnv[j];
    float bscale = rsqrtf(vv + BN_EPS) * gm;
#pragma unroll
    for (int r = 0; r < 16; r++) {
        int row = row0 + r;
        if (row >= n) continue;
        float sc = 1.0f / fmaxf(sqrtf(red[r]), 1e-12f);
        float val = elu_f((v[r] * sc - mm) * bscale + gb);
        out[(size_t)row * HID + j] = val;
        hs [(size_t)row * HID + j] = __float2bfloat16(val);
    }
}

// ---------------------------------------------------------------------------
// tf32 mma.sync fused GEMM — R5-proven inner loop (ASTR=20, single buffer)
//   C[64, 384] = A1 * W1^T (+ A2 * W2^T) + bias
//   epi 0: L2-normalize row, BN, ELU (+ optional bf16 shadow)
//   epi 1: BN, ReLU
//   epi 2: BN, ReLU, then out3 = h @ Wp2^T + bp2 (writes [N,3] only)
// ---------------------------------------------------------------------------
#define ASTR 20

__global__ void __launch_bounds__(512, 1)
k_mma(const float* __restrict__ A1, const float* __restrict__ W1,
      const float* __restrict__ bias,
      const float* __restrict__ A2, const float* __restrict__ W2,
      const float* __restrict__ bng, const float* __restrict__ bnb,
      const float* __restrict__ bnm, const float* __restrict__ bnv,
      float* __restrict__ out, int nrows, int epi,
      __nv_bfloat16* __restrict__ hs,
      const float* __restrict__ Wp2, const float* __restrict__ bp2) {
    __shared__ float As[64 * ASTR];
    __shared__ float Ws[384 * ASTR];
    __shared__ float sSB[HID], sS2[HID], sAD[HID];
    __shared__ float sWp[3 * HID];
    __shared__ float red[64];
    __shared__ float redF[192];

    const int tid  = threadIdx.x;
    const int lane = tid & 31;
    const int wid  = tid >> 5;
    const int rw   = wid & 1;
    const int cw   = wid >> 1;
    const int g    = lane >> 2;
    const int t4   = lane & 3;
    const int warpRow = rw * 32;
    const int cb   = cw * 48;
    const int rb   = blockIdx.x * 64;

    for (int c = tid; c < HID; c += 512) {
        float s2 = rsqrtf(bnv[c] + BN_EPS) * bng[c];
        sSB[c] = bias[c];
        sS2[c] = s2;
        sAD[c] = bnb[c] - bnm[c] * s2;
    }
    if (tid < 64) red[tid] = 0.0f;
    if (tid < 192) redF[tid] = 0.0f;
    if (epi == 2)
        for (int c = tid; c < 3 * HID; c += 512) sWp[c] = Wp2[c];
    __syncthreads();

    const int ar = tid >> 2, aq = tid & 3;
    int wr_[3], wq_[3];
#pragma unroll
    for (int i = 0; i < 3; i++) {
        int idx = tid + i * 512;
        wr_[i] = idx >> 2;
        wq_[i] = idx & 3;
    }

    const int npass = (A2 == nullptr) ? 1 : 2;
    const int S = 24 * npass;

    float acc[2][6][4];
#pragma unroll
    for (int mt = 0; mt < 2; mt++)
#pragma unroll
        for (int nt = 0; nt < 6; nt++)
#pragma unroll
            for (int q = 0; q < 4; q++) acc[mt][nt][q] = 0.0f;

    float4 avP = make_float4(0.f, 0.f, 0.f, 0.f);
    float4 wvP[3];

    {
        if (tid < 256) {
            int row = rb + ar;
            if (row < nrows)
                avP = *(const float4*)(A1 + (size_t)row * HID + aq * 4);
        }
#pragma unroll
        for (int i = 0; i < 3; i++)
            wvP[i] = *(const float4*)(W1 + (size_t)wr_[i] * HID + wq_[i] * 4);
    }

    for (int it = 0; it < S; it++) {
        if (tid < 256) {
            uint32_t* p = (uint32_t*)&As[ar * ASTR + aq * 4];
            p[0] = f2tf32(avP.x); p[1] = f2tf32(avP.y);
            p[2] = f2tf32(avP.z); p[3] = f2tf32(avP.w);
        }
#pragma unroll
        for (int i = 0; i < 3; i++) {
            uint32_t* p = (uint32_t*)&Ws[wr_[i] * ASTR + wq_[i] * 4];
            p[0] = f2tf32(wvP[i].x); p[1] = f2tf32(wvP[i].y);
            p[2] = f2tf32(wvP[i].z); p[3] = f2tf32(wvP[i].w);
        }
        __syncthreads();

        if (it + 1 < S) {
            const int itn = it + 1;
            const int pass = itn / 24;
            const int k0 = (itn % 24) * 16;
            const float* A = pass ? A2 : A1;
            const float* W = pass ? W2 : W1;
            if (tid < 256) {
                int row = rb + ar;
                avP = make_float4(0.f, 0.f, 0.f, 0.f);
                if (row < nrows)
                    avP = *(const float4*)(A + (size_t)row * HID + k0 + aq * 4);
            }
#pragma unroll
            for (int i = 0; i < 3; i++)
                wvP[i] = *(const float4*)(W + (size_t)wr_[i] * HID + k0 + wq_[i] * 4);
        }

#pragma unroll
        for (int ks = 0; ks < 2; ks++) {
            const int kk = ks * 8 + t4;
            uint32_t a[2][4];
#pragma unroll
            for (int mt = 0; mt < 2; mt++) {
                int r0 = warpRow + mt * 16 + g;
                a[mt][0] = __float_as_uint(As[r0 * ASTR + kk]);
                a[mt][1] = __float_as_uint(As[(r0 + 8) * ASTR + kk]);
                a[mt][2] = __float_as_uint(As[r0 * ASTR + kk + 4]);
                a[mt][3] = __float_as_uint(As[(r0 + 8) * ASTR + kk + 4]);
            }
#pragma unroll
            for (int nt = 0; nt < 6; nt++) {
                int n0 = cb + nt * 8 + g;
                uint32_t b0 = __float_as_uint(Ws[n0 * ASTR + kk]);
                uint32_t b1 = __float_as_uint(Ws[n0 * ASTR + kk + 4]);
                mma_tf32(acc[0][nt], a[0][0], a[0][1], a[0][2], a[0][3], b0, b1);
                mma_tf32(acc[1][nt], a[1][0], a[1][1], a[1][2], a[1][3], b0, b1);
            }
        }
        __syncthreads();
    }

    // ---- epilogue ----
#pragma unroll
    for (int nt = 0; nt < 6; nt++) {
        int col = cb + nt * 8 + 2 * t4;
        float b0 = sSB[col], b1 = sSB[col + 1];
#pragma unroll
        for (int mt = 0; mt < 2; mt++) {
            acc[mt][nt][0] += b0; acc[mt][nt][1] += b1;
            acc[mt][nt][2] += b0; acc[mt][nt][3] += b1;
        }
    }

    float sc0[2] = {1.0f, 1.0f}, sc1[2] = {1.0f, 1.0f};
    if (epi == 0) {
#pragma unroll
        for (int mt = 0; mt < 2; mt++) {
            float s0 = 0.0f, s1 = 0.0f;
#pragma unroll
            for (int nt = 0; nt < 6; nt++) {
                s0 = fmaf(acc[mt][nt][0], acc[mt][nt][0], s0);
                s0 = fmaf(acc[mt][nt][1], acc[mt][nt][1], s0);
                s1 = fmaf(acc[mt][nt][2], acc[mt][nt][2], s1);
                s1 = fmaf(acc[mt][nt][3], acc[mt][nt][3], s1);
            }
            s0 += __shfl_xor_sync(0xFFFFFFFFu, s0, 1);
            s0 += __shfl_xor_sync(0xFFFFFFFFu, s0, 2);
            s1 += __shfl_xor_sync(0xFFFFFFFFu, s1, 1);
            s1 += __shfl_xor_sync(0xFFFFFFFFu, s1, 2);
            if (t4 == 0) {
                atomicAdd(&red[warpRow + mt * 16 + g], s0);
                atomicAdd(&red[warpRow + mt * 16 + g + 8], s1);
            }
        }
        __syncthreads();
#pragma unroll
        for (int mt = 0; mt < 2; mt++) {
            sc0[mt] = 1.0f / fmaxf(sqrtf(red[warpRow + mt * 16 + g]), 1e-12f);
            sc1[mt] = 1.0f / fmaxf(sqrtf(red[warpRow + mt * 16 + g + 8]), 1e-12f);
        }
    }

    if (epi == 2) {
        float p0[2][3], p1[2][3];
#pragma unroll
        for (int mt = 0; mt < 2; mt++)
#pragma unroll
            for (int o = 0; o < 3; o++) { p0[mt][o] = 0.0f; p1[mt][o] = 0.0f; }

#pragma unroll
        for (int mt = 0; mt < 2; mt++) {
#pragma unroll
            for (int nt = 0; nt < 6; nt++) {
                int col = cb + nt * 8 + 2 * t4;
                float m0 = sS2[col], m1 = sS2[col + 1];
                float d0 = sAD[col], d1 = sAD[col + 1];
                float x0 = fmaxf(acc[mt][nt][0] * m0 + d0, 0.0f);
                float x1 = fmaxf(acc[mt][nt][1] * m1 + d1, 0.0f);
                float x2 = fmaxf(acc[mt][nt][2] * m0 + d0, 0.0f);
                float x3 = fmaxf(acc[mt][nt][3] * m1 + d1, 0.0f);
#pragma unroll
                for (int o = 0; o < 3; o++) {
                    float w0 = sWp[o * HID + col], w1 = sWp[o * HID + col + 1];
                    p0[mt][o] = fmaf(x0, w0, fmaf(x1, w1, p0[mt][o]));
                    p1[mt][o] = fmaf(x2, w0, fmaf(x3, w1, p1[mt][o]));
                }
            }
        }
#pragma unroll
        for (int mt = 0; mt < 2; mt++)
#pragma unroll
            for (int o = 0; o < 3; o++) {
                float v0 = p0[mt][o], v1 = p1[mt][o];
                v0 += __shfl_xor_sync(0xFFFFFFFFu, v0, 1);
                v0 += __shfl_xor_sync(0xFFFFFFFFu, v0, 2);
                v1 += __shfl_xor_sync(0xFFFFFFFFu, v1, 1);
                v1 += __shfl_xor_sync(0xFFFFFFFFu, v1, 2);
                if (t4 == 0) {
                    atomicAdd(&redF[(warpRow + mt * 16 + g) * 3 + o], v0);
                    atomicAdd(&redF[(warpRow + mt * 16 + g + 8) * 3 + o], v1);
                }
            }
        __syncthreads();
        if (tid < 64) {
            int row = rb + tid;
            if (row < nrows) {
                out[(size_t)row * 3 + 0] = redF[tid * 3 + 0] + bp2[0];
                out[(size_t)row * 3 + 1] = redF[tid * 3 + 1] + bp2[1];
                out[(size_t)row * 3 + 2] = redF[tid * 3 + 2] + bp2[2];
            }
        }
        return;
    }

#pragma unroll
    for (int mt = 0; mt < 2; mt++) {
        int row0 = rb + warpRow + mt * 16 + g;
        int row1 = row0 + 8;
        bool v0r = (row0 < nrows), v1r = (row1 < nrows);
#pragma unroll
        for (int nt = 0; nt < 6; nt++) {
            int col = cb + nt * 8 + 2 * t4;
            float m0 = sS2[col], m1 = sS2[col + 1];
            float d0 = sAD[col], d1 = sAD[col + 1];
            float x0 = acc[mt][nt][0] * sc0[mt] * m0 + d0;
            float x1 = acc[mt][nt][1] * sc0[mt] * m1 + d1;
            float x2 = acc[mt][nt][2] * sc1[mt] * m0 + d0;
            float x3 = acc[mt][nt][3] * sc1[mt] * m1 + d1;
            if (epi == 0) {
                x0 = elu_f(x0); x1 = elu_f(x1);
                x2 = elu_f(x2); x3 = elu_f(x3);
            } else {
                x0 = fmaxf(x0, 0.0f); x1 = fmaxf(x1, 0.0f);
                x2 = fmaxf(x2, 0.0f); x3 = fmaxf(x3, 0.0f);
            }
            if (v0r) {
                *(float2*)(out + (size_t)row0 * HID + col) = make_float2(x0, x1);
                if (hs) *(__nv_bfloat162*)(hs + (size_t)row0 * HID + col) =
                            __floats2bfloat162_rn(x0, x1);
            }
            if (v1r) {
                *(float2*)(out + (size_t)row1 * HID + col) = make_float2(x2, x3);
                if (hs) *(__nv_bfloat162*)(hs + (size_t)row1 * HID + col) =
                            __floats2bfloat162_rn(x2, x3);
            }
        }
    }
}

// ---------------------------------------------------------------------------
extern "C" void kernel_launch(void* const* d_in, const int* in_sizes, int n_in,
                              void* d_out, int out_size) {
    const float* x    = (const float*)d_in[0];
    const int*   ei   = (const int*)  d_in[1];
    const float* Wl0  = (const float*)d_in[2];
    const float* bl0  = (const float*)d_in[3];
    const float* Wr0  = (const float*)d_in[4];
    const float* Wl   = (const float*)d_in[5];
    const float* bl   = (const float*)d_in[6];
    const float* Wr   = (const float*)d_in[7];
    const float* bng  = (const float*)d_in[8];
    const float* bnb  = (const float*)d_in[9];
    const float* bnm  = (const float*)d_in[10];
    const float* bnv  = (const float*)d_in[11];
    const float* Wp0  = (const float*)d_in[12];
    const float* bp0  = (const float*)d_in[13];
    const float* Wp1  = (const float*)d_in[14];
    const float* bp1  = (const float*)d_in[15];
    const float* Wp2  = (const float*)d_in[16];
    const float* bp2  = (const float*)d_in[17];
    const float* pg   = (const float*)d_in[18];
    const float* pb   = (const float*)d_in[19];
    const float* pm   = (const float*)d_in[20];
    const float* pv   = (const float*)d_in[21];

    const int* src = ei;
    const int* dst = ei + EE;

    float *hA, *hB, *agg;
    __nv_bfloat16 *shA, *shB;
    int *deg, *inc, *rowptr, *cur, *csrc, *bsum;
    cudaGetSymbolAddress((void**)&hA,     g_bufA);
    cudaGetSymbolAddress((void**)&hB,     g_bufB);
    cudaGetSymbolAddress((void**)&agg,    g_agg);
    cudaGetSymbolAddress((void**)&shA,    g_shA);
    cudaGetSymbolAddress((void**)&shB,    g_shB);
    cudaGetSymbolAddress((void**)&deg,    g_deg);
    cudaGetSymbolAddress((void**)&inc,    g_inc);
    cudaGetSymbolAddress((void**)&rowptr, g_rowptr);
    cudaGetSymbolAddress((void**)&cur,    g_cur);
    cudaGetSymbolAddress((void**)&csrc,   g_csrc);
    cudaGetSymbolAddress((void**)&bsum,   g_bsum);

    // ---- CSR build ----
    cudaMemsetAsync(deg, 0, NN * sizeof(int));
    k_hist<<<(EE + 255) / 256, 256>>>(dst, deg, EE);
    k_scan_block<<<NSCANB, SCAN_B>>>(deg, inc, bsum, NN);
    k_scan_bsum<<<1, 128>>>(bsum, NSCANB);
    k_csr_fin<<<(NN + 255) / 256, 256>>>(deg, inc, bsum, rowptr, cur, NN);
    k_fill<<<(EE + 255) / 256, 256>>>(src, dst, cur, csrc, EE);

    // ---- layer 0 (K=10) ----
    k_gather10<<<(NN * IN_DIM + 255) / 256, 256>>>(rowptr, csrc, x, agg, NN);
    k_layer0<<<(NN + 15) / 16, 384>>>(agg, x, Wl0, bl0, Wr0,
                                      bng, bnb, bnm, bnv, hA, shA, NN);

    // ---- layers 1..4: bf16 gather + dual tf32 mma GEMM ----
    const int gblocks = (NN + 63) / 64;
    for (int t = 1; t < TT; t++) {
        k_gather384<<<(NN * 32 + 255) / 256, 256>>>(rowptr, csrc, shA, agg, NN);
        k_mma<<<gblocks, 512>>>(
            agg, Wl + (size_t)(t - 1) * HID * HID, bl + (t - 1) * HID,
            hA,  Wr + (size_t)(t - 1) * HID * HID,
            bng + t * HID, bnb + t * HID, bnm + t * HID, bnv + t * HID,
            hB, NN, 0, (t < TT - 1) ? shB : nullptr, nullptr, nullptr);
        float* tf = hA; hA = hB; hB = tf;
        __nv_bfloat16* ts = shA; shA = shB; shB = ts;
    }

    // ---- projection MLP (final [384->3] fused into second GEMM) ----
    k_mma<<<gblocks, 512>>>(hA, Wp0, bp0, nullptr, nullptr,
                            pg, pb, pm, pv, hB, NN, 1,
                            nullptr, nullptr, nullptr);
    k_mma<<<gblocks, 512>>>(hB, Wp1, bp1, nullptr, nullptr,
                            pg + HID, pb + HID, pm + HID, pv + HID,
                            (float*)d_out, NN, 2,
                            nullptr, Wp2, bp2);

    (void)in_sizes; (void)n_in; (void)out_size;
}

// round 8
// speedup vs baseline: 1.5142x; 1.3553x over previous
#include <cuda_runtime.h>
#include <cuda_fp16.h>
#include <math.h>
#include <cstdint>

#define NN 100000
#define EE 300000
#define IN_DIM 10
#define HID 384
#define TT 5
#define BN_EPS 1e-5f

#define SCAN_B 1024
#define NSCANB ((NN + SCAN_B - 1) / SCAN_B)   // 98

// Static scratch (allocation-free rule)
__device__ float   g_bufA[(size_t)NN * HID];
__device__ float   g_bufB[(size_t)NN * HID];
__device__ float   g_agg [(size_t)NN * HID];
__device__ __half  g_shA [(size_t)NN * HID];
__device__ __half  g_shB [(size_t)NN * HID];
__device__ int   g_deg [NN];
__device__ int   g_inc [NN];
__device__ int   g_rowptr[NN + 1];
__device__ int   g_cur [NN];
__device__ int   g_csrc[EE];
__device__ int   g_bsum[128];

// ---------------------------------------------------------------------------
// helpers
// ---------------------------------------------------------------------------
__device__ __forceinline__ void mma_f16(float* c, uint32_t a0, uint32_t a1,
                                        uint32_t a2, uint32_t a3,
                                        uint32_t b0, uint32_t b1) {
    asm volatile("mma.sync.aligned.m16n8k16.row.col.f32.f16.f16.f32 "
                 "{%0,%1,%2,%3}, {%4,%5,%6,%7}, {%8,%9}, {%0,%1,%2,%3};"
                 : "+f"(c[0]), "+f"(c[1]), "+f"(c[2]), "+f"(c[3])
                 : "r"(a0), "r"(a1), "r"(a2), "r"(a3), "r"(b0), "r"(b1));
}

__device__ __forceinline__ float elu_f(float v) {
    return (v > 0.0f) ? v : (__expf(v) - 1.0f);
}

__device__ __forceinline__ uint32_t h2pack(float x, float y) {
    __half2 h = __float22half2_rn(make_float2(x, y));
    return *(uint32_t*)&h;
}

// ---------------------------------------------------------------------------
// CSR build
// ---------------------------------------------------------------------------
__global__ void k_hist(const int* __restrict__ dst, int* __restrict__ deg, int e) {
    int i = blockIdx.x * blockDim.x + threadIdx.x;
    if (i < e) atomicAdd(&deg[dst[i]], 1);
}

__global__ void k_scan_block(const int* __restrict__ deg, int* __restrict__ inc,
                             int* __restrict__ bsum, int n) {
    __shared__ int s[SCAN_B];
    int i = blockIdx.x * SCAN_B + threadIdx.x;
    s[threadIdx.x] = (i < n) ? deg[i] : 0;
    __syncthreads();
#pragma unroll
    for (int o = 1; o < SCAN_B; o <<= 1) {
        int t = (threadIdx.x >= o) ? s[threadIdx.x - o] : 0;
        __syncthreads();
        s[threadIdx.x] += t;
        __syncthreads();
    }
    if (i < n) inc[i] = s[threadIdx.x];
    if (threadIdx.x == SCAN_B - 1) bsum[blockIdx.x] = s[SCAN_B - 1];
}

__global__ void k_scan_bsum(int* __restrict__ bsum, int nb) {
    __shared__ int s[128];
    if (threadIdx.x < nb) s[threadIdx.x] = bsum[threadIdx.x];
    __syncthreads();
    if (threadIdx.x == 0) {
        int run = 0;
        for (int i = 0; i < nb; i++) { run += s[i]; s[i] = run; }
    }
    __syncthreads();
    if (threadIdx.x < nb) bsum[threadIdx.x] = s[threadIdx.x];
}

__global__ void k_csr_fin(const int* __restrict__ deg, const int* __restrict__ inc,
                          const int* __restrict__ bsum,
                          int* __restrict__ rowptr, int* __restrict__ cur, int n) {
    int i = blockIdx.x * blockDim.x + threadIdx.x;
    if (i >= n) return;
    int b = i / SCAN_B;
    int total = inc[i] + (b > 0 ? bsum[b - 1] : 0);
    rowptr[i + 1] = total;
    cur[i] = total - deg[i];
    if (i == 0) rowptr[0] = 0;
}

__global__ void k_fill(const int* __restrict__ src, const int* __restrict__ dst,
                       int* __restrict__ cur, int* __restrict__ csrc, int e) {
    int i = blockIdx.x * blockDim.x + threadIdx.x;
    if (i >= e) return;
    int pos = atomicAdd(&cur[dst[i]], 1);
    csrc[pos] = src[i];
}

// ---------------------------------------------------------------------------
// CSR mean-gather, width 384, fp16 source, fp32 accumulate, 2x unroll
// ---------------------------------------------------------------------------
__global__ void k_gather384(const int* __restrict__ rowptr, const int* __restrict__ csrc,
                            const __half* __restrict__ hs, float* __restrict__ agg,
                            int n) {
    int node = (blockIdx.x * blockDim.x + threadIdx.x) >> 5;
    int lane = threadIdx.x & 31;
    if (node >= n) return;
    int beg = rowptr[node], end = rowptr[node + 1];
    float a[12], b[12];
#pragma unroll
    for (int i = 0; i < 12; i++) { a[i] = 0.0f; b[i] = 0.0f; }

    int e = beg;
    for (; e + 1 < end; e += 2) {
        int s0 = csrc[e], s1 = csrc[e + 1];
        const uint2* p0 = (const uint2*)(hs + (size_t)s0 * HID) + lane;
        const uint2* p1 = (const uint2*)(hs + (size_t)s1 * HID) + lane;
        uint2 u0 = p0[0], u1 = p0[32], u2 = p0[64];
        uint2 w0 = p1[0], w1 = p1[32], w2 = p1[64];
        float2 f;
        f = __half22float2(*(__half2*)&u0.x); a[0] += f.x; a[1] += f.y;
        f = __half22float2(*(__half2*)&u0.y); a[2] += f.x; a[3] += f.y;
        f = __half22float2(*(__half2*)&u1.x); a[4] += f.x; a[5] += f.y;
        f = __half22float2(*(__half2*)&u1.y); a[6] += f.x; a[7] += f.y;
        f = __half22float2(*(__half2*)&u2.x); a[8] += f.x; a[9] += f.y;
        f = __half22float2(*(__half2*)&u2.y); a[10] += f.x; a[11] += f.y;
        f = __half22float2(*(__half2*)&w0.x); b[0] += f.x; b[1] += f.y;
        f = __half22float2(*(__half2*)&w0.y); b[2] += f.x; b[3] += f.y;
        f = __half22float2(*(__half2*)&w1.x); b[4] += f.x; b[5] += f.y;
        f = __half22float2(*(__half2*)&w1.y); b[6] += f.x; b[7] += f.y;
        f = __half22float2(*(__half2*)&w2.x); b[8] += f.x; b[9] += f.y;
        f = __half22float2(*(__half2*)&w2.y); b[10] += f.x; b[11] += f.y;
    }
    if (e < end) {
        const uint2* p0 = (const uint2*)(hs + (size_t)csrc[e] * HID) + lane;
        uint2 u0 = p0[0], u1 = p0[32], u2 = p0[64];
        float2 f;
        f = __half22float2(*(__half2*)&u0.x); a[0] += f.x; a[1] += f.y;
        f = __half22float2(*(__half2*)&u0.y); a[2] += f.x; a[3] += f.y;
        f = __half22float2(*(__half2*)&u1.x); a[4] += f.x; a[5] += f.y;
        f = __half22float2(*(__half2*)&u1.y); a[6] += f.x; a[7] += f.y;
        f = __half22float2(*(__half2*)&u2.x); a[8] += f.x; a[9] += f.y;
        f = __half22float2(*(__half2*)&u2.y); a[10] += f.x; a[11] += f.y;
    }

    float iv = 1.0f / fmaxf((float)(end - beg), 1.0f);
    float4* o = (float4*)(agg + (size_t)node * HID) + lane;
    o[0]  = make_float4((a[0]+b[0])*iv, (a[1]+b[1])*iv, (a[2]+b[2])*iv, (a[3]+b[3])*iv);
    o[32] = make_float4((a[4]+b[4])*iv, (a[5]+b[5])*iv, (a[6]+b[6])*iv, (a[7]+b[7])*iv);
    o[64] = make_float4((a[8]+b[8])*iv, (a[9]+b[9])*iv, (a[10]+b[10])*iv, (a[11]+b[11])*iv);
}

// width 10: thread per (node, feature), fp32 source
__global__ void k_gather10(const int* __restrict__ rowptr, const int* __restrict__ csrc,
                           const float* __restrict__ x, float* __restrict__ agg, int n) {
    int idx = blockIdx.x * blockDim.x + threadIdx.x;
    if (idx >= n * IN_DIM) return;
    int node = idx / IN_DIM, f = idx % IN_DIM;
    int beg = rowptr[node], end = rowptr[node + 1];
    float a = 0.0f;
    for (int e = beg; e < end; e++)
        a += x[(size_t)csrc[e] * IN_DIM + f];
    agg[idx] = a / fmaxf((float)(end - beg), 1.0f);
}

// ---------------------------------------------------------------------------
// Layer 0 SAGE: K=10, 32 rows/block, 384 threads; writes fp32 + fp16 shadow
// ---------------------------------------------------------------------------
#define L0R 32
__global__ void k_layer0(const float* __restrict__ agg, const float* __restrict__ x,
                         const float* __restrict__ Wl, const float* __restrict__ bl,
                         const float* __restrict__ Wr,
                         const float* __restrict__ bng, const float* __restrict__ bnb,
                         const float* __restrict__ bnm, const float* __restrict__ bnv,
                         float* __restrict__ out, __half* __restrict__ hs, int n) {
    __shared__ float sA[L0R][IN_DIM];
    __shared__ float sX[L0R][IN_DIM];
    __shared__ float red[L0R];
    int t = threadIdx.x;
    int row0 = blockIdx.x * L0R;

    if (t < L0R * IN_DIM) {
        int r = t / IN_DIM, k = t % IN_DIM;
        int row = row0 + r;
        sA[r][k] = (row < n) ? agg[(size_t)row * IN_DIM + k] : 0.0f;
        sX[r][k] = (row < n) ? x[(size_t)row * IN_DIM + k] : 0.0f;
    } else if (t < L0R * IN_DIM + L0R) {
        red[t - L0R * IN_DIM] = 0.0f;
    }
    __syncthreads();

    int j = t;
    float wl[IN_DIM], wr[IN_DIM];
#pragma unroll
    for (int k = 0; k < IN_DIM; k++) {
        wl[k] = Wl[j * IN_DIM + k];
        wr[k] = Wr[j * IN_DIM + k];
    }
    float bb = bl[j];

    float v[L0R];
#pragma unroll
    for (int r = 0; r < L0R; r++) {
        float s = bb;
#pragma unroll
        for (int k = 0; k < IN_DIM; k++)
            s += sA[r][k] * wl[k] + sX[r][k] * wr[k];
        v[r] = s;
    }

    int lane = t & 31;
#pragma unroll
    for (int r = 0; r < L0R; r++) {
        float p = v[r] * v[r];
#pragma unroll
        for (int o = 16; o > 0; o >>= 1) p += __shfl_xor_sync(0xFFFFFFFFu, p, o);
        if (lane == 0) atomicAdd(&red[r], p);
    }
    __syncthreads();

    float gm = bng[j], gb = bnb[j], mm = bnm[j], vv = bnv[j];
    float bscale = rsqrtf(vv + BN_EPS) * gm;
#pragma unroll
    for (int r = 0; r < L0R; r++) {
        int row = row0 + r;
        if (row >= n) continue;
        float sc = 1.0f / fmaxf(sqrtf(red[r]), 1e-12f);
        float val = elu_f((v[r] * sc - mm) * bscale + gb);
        out[(size_t)row * HID + j] = val;
        hs [(size_t)row * HID + j] = __float2half(val);
    }
}

// ---------------------------------------------------------------------------
// fp16 mma.sync m16n8k16 fused GEMM — same structure as proven tf32 loop
//   C[64, 384] = A1 * W1^T (+ A2 * W2^T) + bias
//   epi 0: L2-normalize row, BN, ELU (+ optional fp16 shadow)
//   epi 1: BN, ReLU
//   epi 2: BN, ReLU, then out3 = h @ Wp2^T + bp2 (writes [N,3] only)
// SMEM: halves, row stride 24 halves (48B) — frag loads conflict-free
// ---------------------------------------------------------------------------
#define HSTR 24

__global__ void __launch_bounds__(512, 1)
k_mma(const float* __restrict__ A1, const float* __restrict__ W1,
      const float* __restrict__ bias,
      const float* __restrict__ A2, const float* __restrict__ W2,
      const float* __restrict__ bng, const float* __restrict__ bnb,
      const float* __restrict__ bnm, const float* __restrict__ bnv,
      float* __restrict__ out, int nrows, int epi,
      __half* __restrict__ hs,
      const float* __restrict__ Wp2, const float* __restrict__ bp2) {
    __shared__ __half As[64 * HSTR];
    __shared__ __half Ws[384 * HSTR];
    __shared__ float sSB[HID], sS2[HID], sAD[HID];
    __shared__ float sWp[3 * HID];
    __shared__ float red[64];
    __shared__ float redF[192];

    const int tid  = threadIdx.x;
    const int lane = tid & 31;
    const int wid  = tid >> 5;
    const int rw   = wid & 1;
    const int cw   = wid >> 1;
    const int g    = lane >> 2;
    const int t4   = lane & 3;
    const int warpRow = rw * 32;
    const int cb   = cw * 48;
    const int rb   = blockIdx.x * 64;

    for (int c = tid; c < HID; c += 512) {
        float s2 = rsqrtf(bnv[c] + BN_EPS) * bng[c];
        sSB[c] = bias[c];
        sS2[c] = s2;
        sAD[c] = bnb[c] - bnm[c] * s2;
    }
    if (tid < 64) red[tid] = 0.0f;
    if (tid < 192) redF[tid] = 0.0f;
    if (epi == 2)
        for (int c = tid; c < 3 * HID; c += 512) sWp[c] = Wp2[c];
    __syncthreads();

    const int ar = tid >> 2, aq = tid & 3;
    int wr_[3], wq_[3];
#pragma unroll
    for (int i = 0; i < 3; i++) {
        int idx = tid + i * 512;
        wr_[i] = idx >> 2;
        wq_[i] = idx & 3;
    }

    const int npass = (A2 == nullptr) ? 1 : 2;
    const int S = 24 * npass;

    float acc[2][6][4];
#pragma unroll
    for (int mt = 0; mt < 2; mt++)
#pragma unroll
        for (int nt = 0; nt < 6; nt++)
#pragma unroll
            for (int q = 0; q < 4; q++) acc[mt][nt][q] = 0.0f;

    float4 avP = make_float4(0.f, 0.f, 0.f, 0.f);
    float4 wvP[3];

    {
        if (tid < 256) {
            int row = rb + ar;
            if (row < nrows)
                avP = *(const float4*)(A1 + (size_t)row * HID + aq * 4);
        }
#pragma unroll
        for (int i = 0; i < 3; i++)
            wvP[i] = *(const float4*)(W1 + (size_t)wr_[i] * HID + wq_[i] * 4);
    }

    for (int it = 0; it < S; it++) {
        // stage to SMEM as fp16 (uint2 = 4 halves)
        if (tid < 256) {
            uint2* p = (uint2*)&As[ar * HSTR + aq * 4];
            p->x = h2pack(avP.x, avP.y);
            p->y = h2pack(avP.z, avP.w);
        }
#pragma unroll
        for (int i = 0; i < 3; i++) {
            uint2* p = (uint2*)&Ws[wr_[i] * HSTR + wq_[i] * 4];
            p->x = h2pack(wvP[i].x, wvP[i].y);
            p->y = h2pack(wvP[i].z, wvP[i].w);
        }
        __syncthreads();

        // prefetch next chunk
        if (it + 1 < S) {
            const int itn = it + 1;
            const int pass = itn / 24;
            const int k0 = (itn % 24) * 16;
            const float* A = pass ? A2 : A1;
            const float* W = pass ? W2 : W1;
            if (tid < 256) {
                int row = rb + ar;
                avP = make_float4(0.f, 0.f, 0.f, 0.f);
                if (row < nrows)
                    avP = *(const float4*)(A + (size_t)row * HID + k0 + aq * 4);
            }
#pragma unroll
            for (int i = 0; i < 3; i++)
                wvP[i] = *(const float4*)(W + (size_t)wr_[i] * HID + k0 + wq_[i] * 4);
        }

        // compute: one k16 step, 12 MMAs
        {
            uint32_t a[2][4];
#pragma unroll
            for (int mt = 0; mt < 2; mt++) {
                int r0 = warpRow + mt * 16 + g;
                a[mt][0] = *(uint32_t*)&As[r0 * HSTR + t4 * 2];
                a[mt][1] = *(uint32_t*)&As[(r0 + 8) * HSTR + t4 * 2];
                a[mt][2] = *(uint32_t*)&As[r0 * HSTR + t4 * 2 + 8];
                a[mt][3] = *(uint32_t*)&As[(r0 + 8) * HSTR + t4 * 2 + 8];
            }
#pragma unroll
            for (int nt = 0; nt < 6; nt++) {
                int n0 = cb + nt * 8 + g;
                uint32_t b0 = *(uint32_t*)&Ws[n0 * HSTR + t4 * 2];
                uint32_t b1 = *(uint32_t*)&Ws[n0 * HSTR + t4 * 2 + 8];
                mma_f16(acc[0][nt], a[0][0], a[0][1], a[0][2], a[0][3], b0, b1);
                mma_f16(acc[1][nt], a[1][0], a[1][1], a[1][2], a[1][3], b0, b1);
            }
        }
        __syncthreads();
    }

    // ---- epilogue (acc layout identical to m16n8k8) ----
#pragma unroll
    for (int nt = 0; nt < 6; nt++) {
        int col = cb + nt * 8 + 2 * t4;
        float b0 = sSB[col], b1 = sSB[col + 1];
#pragma unroll
        for (int mt = 0; mt < 2; mt++) {
            acc[mt][nt][0] += b0; acc[mt][nt][1] += b1;
            acc[mt][nt][2] += b0; acc[mt][nt][3] += b1;
        }
    }

    float sc0[2] = {1.0f, 1.0f}, sc1[2] = {1.0f, 1.0f};
    if (epi == 0) {
#pragma unroll
        for (int mt = 0; mt < 2; mt++) {
            float s0 = 0.0f, s1 = 0.0f;
#pragma unroll
            for (int nt = 0; nt < 6; nt++) {
                s0 = fmaf(acc[mt][nt][0], acc[mt][nt][0], s0);
                s0 = fmaf(acc[mt][nt][1], acc[mt][nt][1], s0);
                s1 = fmaf(acc[mt][nt][2], acc[mt][nt][2], s1);
                s1 = fmaf(acc[mt][nt][3], acc[mt][nt][3], s1);
            }
            s0 += __shfl_xor_sync(0xFFFFFFFFu, s0, 1);
            s0 += __shfl_xor_sync(0xFFFFFFFFu, s0, 2);
            s1 += __shfl_xor_sync(0xFFFFFFFFu, s1, 1);
            s1 += __shfl_xor_sync(0xFFFFFFFFu, s1, 2);
            if (t4 == 0) {
                atomicAdd(&red[warpRow + mt * 16 + g], s0);
                atomicAdd(&red[warpRow + mt * 16 + g + 8], s1);
            }
        }
        __syncthreads();
#pragma unroll
        for (int mt = 0; mt < 2; mt++) {
            sc0[mt] = 1.0f / fmaxf(sqrtf(red[warpRow + mt * 16 + g]), 1e-12f);
            sc1[mt] = 1.0f / fmaxf(sqrtf(red[warpRow + mt * 16 + g + 8]), 1e-12f);
        }
    }

    if (epi == 2) {
        float p0[2][3], p1[2][3];
#pragma unroll
        for (int mt = 0; mt < 2; mt++)
#pragma unroll
            for (int o = 0; o < 3; o++) { p0[mt][o] = 0.0f; p1[mt][o] = 0.0f; }

#pragma unroll
        for (int mt = 0; mt < 2; mt++) {
#pragma unroll
            for (int nt = 0; nt < 6; nt++) {
                int col = cb + nt * 8 + 2 * t4;
                float m0 = sS2[col], m1 = sS2[col + 1];
                float d0 = sAD[col], d1 = sAD[col + 1];
                float x0 = fmaxf(acc[mt][nt][0] * m0 + d0, 0.0f);
                float x1 = fmaxf(acc[mt][nt][1] * m1 + d1, 0.0f);
                float x2 = fmaxf(acc[mt][nt][2] * m0 + d0, 0.0f);
                float x3 = fmaxf(acc[mt][nt][3] * m1 + d1, 0.0f);
#pragma unroll
                for (int o = 0; o < 3; o++) {
                    float w0 = sWp[o * HID + col], w1 = sWp[o * HID + col + 1];
                    p0[mt][o] = fmaf(x0, w0, fmaf(x1, w1, p0[mt][o]));
                    p1[mt][o] = fmaf(x2, w0, fmaf(x3, w1, p1[mt][o]));
                }
            }
        }
#pragma unroll
        for (int mt = 0; mt < 2; mt++)
#pragma unroll
            for (int o = 0; o < 3; o++) {
                float v0 = p0[mt][o], v1 = p1[mt][o];
                v0 += __shfl_xor_sync(0xFFFFFFFFu, v0, 1);
                v0 += __shfl_xor_sync(0xFFFFFFFFu, v0, 2);
                v1 += __shfl_xor_sync(0xFFFFFFFFu, v1, 1);
                v1 += __shfl_xor_sync(0xFFFFFFFFu, v1, 2);
                if (t4 == 0) {
                    atomicAdd(&redF[(warpRow + mt * 16 + g) * 3 + o], v0);
                    atomicAdd(&redF[(warpRow + mt * 16 + g + 8) * 3 + o], v1);
                }
            }
        __syncthreads();
        if (tid < 64) {
            int row = rb + tid;
            if (row < nrows) {
                out[(size_t)row * 3 + 0] = redF[tid * 3 + 0] + bp2[0];
                out[(size_t)row * 3 + 1] = redF[tid * 3 + 1] + bp2[1];
                out[(size_t)row * 3 + 2] = redF[tid * 3 + 2] + bp2[2];
            }
        }
        return;
    }

#pragma unroll
    for (int mt = 0; mt < 2; mt++) {
        int row0 = rb + warpRow + mt * 16 + g;
        int row1 = row0 + 8;
        bool v0r = (row0 < nrows), v1r = (row1 < nrows);
#pragma unroll
        for (int nt = 0; nt < 6; nt++) {
            int col = cb + nt * 8 + 2 * t4;
            float m0 = sS2[col], m1 = sS2[col + 1];
            float d0 = sAD[col], d1 = sAD[col + 1];
            float x0 = acc[mt][nt][0] * sc0[mt] * m0 + d0;
            float x1 = acc[mt][nt][1] * sc0[mt] * m1 + d1;
            float x2 = acc[mt][nt][2] * sc1[mt] * m0 + d0;
            float x3 = acc[mt][nt][3] * sc1[mt] * m1 + d1;
            if (epi == 0) {
                x0 = elu_f(x0); x1 = elu_f(x1);
                x2 = elu_f(x2); x3 = elu_f(x3);
            } else {
                x0 = fmaxf(x0, 0.0f); x1 = fmaxf(x1, 0.0f);
                x2 = fmaxf(x2, 0.0f); x3 = fmaxf(x3, 0.0f);
            }
            if (v0r) {
                *(float2*)(out + (size_t)row0 * HID + col) = make_float2(x0, x1);
                if (hs) *(uint32_t*)(hs + (size_t)row0 * HID + col) = h2pack(x0, x1);
            }
            if (v1r) {
                *(float2*)(out + (size_t)row1 * HID + col) = make_float2(x2, x3);
                if (hs) *(uint32_t*)(hs + (size_t)row1 * HID + col) = h2pack(x2, x3);
            }
        }
    }
}

// ---------------------------------------------------------------------------
extern "C" void kernel_launch(void* const* d_in, const int* in_sizes, int n_in,
                              void* d_out, int out_size) {
    const float* x    = (const float*)d_in[0];
    const int*   ei   = (const int*)  d_in[1];
    const float* Wl0  = (const float*)d_in[2];
    const float* bl0  = (const float*)d_in[3];
    const float* Wr0  = (const float*)d_in[4];
    const float* Wl   = (const float*)d_in[5];
    const float* bl   = (const float*)d_in[6];
    const float* Wr   = (const float*)d_in[7];
    const float* bng  = (const float*)d_in[8];
    const float* bnb  = (const float*)d_in[9];
    const float* bnm  = (const float*)d_in[10];
    const float* bnv  = (const float*)d_in[11];
    const float* Wp0  = (const float*)d_in[12];
    const float* bp0  = (const float*)d_in[13];
    const float* Wp1  = (const float*)d_in[14];
    const float* bp1  = (const float*)d_in[15];
    const float* Wp2  = (const float*)d_in[16];
    const float* bp2  = (const float*)d_in[17];
    const float* pg   = (const float*)d_in[18];
    const float* pb   = (const float*)d_in[19];
    const float* pm   = (const float*)d_in[20];
    const float* pv   = (const float*)d_in[21];

    const int* src = ei;
    const int* dst = ei + EE;

    float *hA, *hB, *agg;
    __half *shA, *shB;
    int *deg, *inc, *rowptr, *cur, *csrc, *bsum;
    cudaGetSymbolAddress((void**)&hA,     g_bufA);
    cudaGetSymbolAddress((void**)&hB,     g_bufB);
    cudaGetSymbolAddress((void**)&agg,    g_agg);
    cudaGetSymbolAddress((void**)&shA,    g_shA);
    cudaGetSymbolAddress((void**)&shB,    g_shB);
    cudaGetSymbolAddress((void**)&deg,    g_deg);
    cudaGetSymbolAddress((void**)&inc,    g_inc);
    cudaGetSymbolAddress((void**)&rowptr, g_rowptr);
    cudaGetSymbolAddress((void**)&cur,    g_cur);
    cudaGetSymbolAddress((void**)&csrc,   g_csrc);
    cudaGetSymbolAddress((void**)&bsum,   g_bsum);

    // ---- CSR build ----
    cudaMemsetAsync(deg, 0, NN * sizeof(int));
    k_hist<<<(EE + 255) / 256, 256>>>(dst, deg, EE);
    k_scan_block<<<NSCANB, SCAN_B>>>(deg, inc, bsum, NN);
    k_scan_bsum<<<1, 128>>>(bsum, NSCANB);
    k_csr_fin<<<(NN + 255) / 256, 256>>>(deg, inc, bsum, rowptr, cur, NN);
    k_fill<<<(EE + 255) / 256, 256>>>(src, dst, cur, csrc, EE);

    // ---- layer 0 (K=10) ----
    k_gather10<<<(NN * IN_DIM + 255) / 256, 256>>>(rowptr, csrc, x, agg, NN);
    k_layer0<<<(NN + L0R - 1) / L0R, 384>>>(agg, x, Wl0, bl0, Wr0,
                                            bng, bnb, bnm, bnv, hA, shA, NN);

    // ---- layers 1..4: fp16 gather + dual fp16 mma GEMM ----
    const int gblocks = (NN + 63) / 64;
    for (int t = 1; t < TT; t++) {
        k_gather384<<<(NN * 32 + 255) / 256, 256>>>(rowptr, csrc, shA, agg, NN);
        k_mma<<<gblocks, 512>>>(
            agg, Wl + (size_t)(t - 1) * HID * HID, bl + (t - 1) * HID,
            hA,  Wr + (size_t)(t - 1) * HID * HID,
            bng + t * HID, bnb + t * HID, bnm + t * HID, bnv + t * HID,
            hB, NN, 0, (t < TT - 1) ? shB : nullptr, nullptr, nullptr);
        float* tf = hA; hA = hB; hB = tf;
        __half* ts = shA; shA = shB; shB = ts;
    }

    // ---- projection MLP (final [384->3] fused into second GEMM) ----
    k_mma<<<gblocks, 512>>>(hA, Wp0, bp0, nullptr, nullptr,
                            pg, pb, pm, pv, hB, NN, 1,
                            nullptr, nullptr, nullptr);
    k_mma<<<gblocks, 512>>>(hB, Wp1, bp1, nullptr, nullptr,
                            pg + HID, pb + HID, pm + HID, pv + HID,
                            (float*)d_out, NN, 2,
                            nullptr, Wp2, bp2);

    (void)in_sizes; (void)n_in; (void)out_size;
}

// round 9
// speedup vs baseline: 1.6965x; 1.1204x over previous
#include <cuda_runtime.h>
#include <cuda_fp16.h>
#include <math.h>
#include <cstdint>

#define NN 100000
#define EE 300000
#define IN_DIM 10
#define HID 384
#define TT 5
#define BN_EPS 1e-5f
#define WMAT (HID * HID)

#define SCAN_B 1024
#define NSCANB ((NN + SCAN_B - 1) / SCAN_B)   // 98

// Static scratch (allocation-free rule) — all activations fp16
__device__ __half  g_agg16[(size_t)NN * HID];
__device__ __half  g_shA [(size_t)NN * HID];
__device__ __half  g_shB [(size_t)NN * HID];
__device__ float   g_agg10[(size_t)NN * IN_DIM];
__device__ __half  g_wl16[4 * WMAT];
__device__ __half  g_wr16[4 * WMAT];
__device__ __half  g_wp016[WMAT];
__device__ __half  g_wp116[WMAT];
__device__ int   g_deg [NN];
__device__ int   g_inc [NN];
__device__ int   g_rowptr[NN + 1];
__device__ int   g_cur [NN];
__device__ int   g_csrc[EE];
__device__ int   g_bsum[128];

// ---------------------------------------------------------------------------
// helpers
// ---------------------------------------------------------------------------
__device__ __forceinline__ void mma_f16(float* c, uint32_t a0, uint32_t a1,
                                        uint32_t a2, uint32_t a3,
                                        uint32_t b0, uint32_t b1) {
    asm volatile("mma.sync.aligned.m16n8k16.row.col.f32.f16.f16.f32 "
                 "{%0,%1,%2,%3}, {%4,%5,%6,%7}, {%8,%9}, {%0,%1,%2,%3};"
                 : "+f"(c[0]), "+f"(c[1]), "+f"(c[2]), "+f"(c[3])
                 : "r"(a0), "r"(a1), "r"(a2), "r"(a3), "r"(b0), "r"(b1));
}

__device__ __forceinline__ float elu_f(float v) {
    return (v > 0.0f) ? v : (__expf(v) - 1.0f);
}

__device__ __forceinline__ uint32_t h2pack(float x, float y) {
    __half2 h = __float22half2_rn(make_float2(x, y));
    return *(uint32_t*)&h;
}

// fp32 -> fp16 weight conversion (vectorized)
__global__ void k_cvt4(const float4* __restrict__ src, uint2* __restrict__ dst, int n4) {
    int i = blockIdx.x * blockDim.x + threadIdx.x;
    if (i >= n4) return;
    float4 v = src[i];
    uint2 o;
    o.x = h2pack(v.x, v.y);
    o.y = h2pack(v.z, v.w);
    dst[i] = o;
}

// ---------------------------------------------------------------------------
// CSR build
// ---------------------------------------------------------------------------
__global__ void k_hist(const int* __restrict__ dst, int* __restrict__ deg, int e) {
    int i = blockIdx.x * blockDim.x + threadIdx.x;
    if (i < e) atomicAdd(&deg[dst[i]], 1);
}

__global__ void k_scan_block(const int* __restrict__ deg, int* __restrict__ inc,
                             int* __restrict__ bsum, int n) {
    __shared__ int s[SCAN_B];
    int i = blockIdx.x * SCAN_B + threadIdx.x;
    s[threadIdx.x] = (i < n) ? deg[i] : 0;
    __syncthreads();
#pragma unroll
    for (int o = 1; o < SCAN_B; o <<= 1) {
        int t = (threadIdx.x >= o) ? s[threadIdx.x - o] : 0;
        __syncthreads();
        s[threadIdx.x] += t;
        __syncthreads();
    }
    if (i < n) inc[i] = s[threadIdx.x];
    if (threadIdx.x == SCAN_B - 1) bsum[blockIdx.x] = s[SCAN_B - 1];
}

__global__ void k_scan_bsum(int* __restrict__ bsum, int nb) {
    __shared__ int s[128];
    if (threadIdx.x < nb) s[threadIdx.x] = bsum[threadIdx.x];
    __syncthreads();
    if (threadIdx.x == 0) {
        int run = 0;
        for (int i = 0; i < nb; i++) { run += s[i]; s[i] = run; }
    }
    __syncthreads();
    if (threadIdx.x < nb) bsum[threadIdx.x] = s[threadIdx.x];
}

__global__ void k_csr_fin(const int* __restrict__ deg, const int* __restrict__ inc,
                          const int* __restrict__ bsum,
                          int* __restrict__ rowptr, int* __restrict__ cur, int n) {
    int i = blockIdx.x * blockDim.x + threadIdx.x;
    if (i >= n) return;
    int b = i / SCAN_B;
    int total = inc[i] + (b > 0 ? bsum[b - 1] : 0);
    rowptr[i + 1] = total;
    cur[i] = total - deg[i];
    if (i == 0) rowptr[0] = 0;
}

__global__ void k_fill(const int* __restrict__ src, const int* __restrict__ dst,
                       int* __restrict__ cur, int* __restrict__ csrc, int e) {
    int i = blockIdx.x * blockDim.x + threadIdx.x;
    if (i >= e) return;
    int pos = atomicAdd(&cur[dst[i]], 1);
    csrc[pos] = src[i];
}

// ---------------------------------------------------------------------------
// CSR mean-gather, width 384, fp16 in/out, fp32 accumulate, 2x unroll
// ---------------------------------------------------------------------------
__global__ void k_gather384(const int* __restrict__ rowptr, const int* __restrict__ csrc,
                            const __half* __restrict__ hs, __half* __restrict__ agg,
                            int n) {
    int node = (blockIdx.x * blockDim.x + threadIdx.x) >> 5;
    int lane = threadIdx.x & 31;
    if (node >= n) return;
    int beg = rowptr[node], end = rowptr[node + 1];
    float a[12], b[12];
#pragma unroll
    for (int i = 0; i < 12; i++) { a[i] = 0.0f; b[i] = 0.0f; }

    int e = beg;
    for (; e + 1 < end; e += 2) {
        int s0 = csrc[e], s1 = csrc[e + 1];
        const uint2* p0 = (const uint2*)(hs + (size_t)s0 * HID) + lane;
        const uint2* p1 = (const uint2*)(hs + (size_t)s1 * HID) + lane;
        uint2 u0 = p0[0], u1 = p0[32], u2 = p0[64];
        uint2 w0 = p1[0], w1 = p1[32], w2 = p1[64];
        float2 f;
        f = __half22float2(*(__half2*)&u0.x); a[0] += f.x; a[1] += f.y;
        f = __half22float2(*(__half2*)&u0.y); a[2] += f.x; a[3] += f.y;
        f = __half22float2(*(__half2*)&u1.x); a[4] += f.x; a[5] += f.y;
        f = __half22float2(*(__half2*)&u1.y); a[6] += f.x; a[7] += f.y;
        f = __half22float2(*(__half2*)&u2.x); a[8] += f.x; a[9] += f.y;
        f = __half22float2(*(__half2*)&u2.y); a[10] += f.x; a[11] += f.y;
        f = __half22float2(*(__half2*)&w0.x); b[0] += f.x; b[1] += f.y;
        f = __half22float2(*(__half2*)&w0.y); b[2] += f.x; b[3] += f.y;
        f = __half22float2(*(__half2*)&w1.x); b[4] += f.x; b[5] += f.y;
        f = __half22float2(*(__half2*)&w1.y); b[6] += f.x; b[7] += f.y;
        f = __half22float2(*(__half2*)&w2.x); b[8] += f.x; b[9] += f.y;
        f = __half22float2(*(__half2*)&w2.y); b[10] += f.x; b[11] += f.y;
    }
    if (e < end) {
        const uint2* p0 = (const uint2*)(hs + (size_t)csrc[e] * HID) + lane;
        uint2 u0 = p0[0], u1 = p0[32], u2 = p0[64];
        float2 f;
        f = __half22float2(*(__half2*)&u0.x); a[0] += f.x; a[1] += f.y;
        f = __half22float2(*(__half2*)&u0.y); a[2] += f.x; a[3] += f.y;
        f = __half22float2(*(__half2*)&u1.x); a[4] += f.x; a[5] += f.y;
        f = __half22float2(*(__half2*)&u1.y); a[6] += f.x; a[7] += f.y;
        f = __half22float2(*(__half2*)&u2.x); a[8] += f.x; a[9] += f.y;
        f = __half22float2(*(__half2*)&u2.y); a[10] += f.x; a[11] += f.y;
    }

    float iv = 1.0f / fmaxf((float)(end - beg), 1.0f);
    uint2* o = (uint2*)(agg + (size_t)node * HID) + lane;
    uint2 r;
    r.x = h2pack((a[0]+b[0])*iv, (a[1]+b[1])*iv);
    r.y = h2pack((a[2]+b[2])*iv, (a[3]+b[3])*iv);
    o[0] = r;
    r.x = h2pack((a[4]+b[4])*iv, (a[5]+b[5])*iv);
    r.y = h2pack((a[6]+b[6])*iv, (a[7]+b[7])*iv);
    o[32] = r;
    r.x = h2pack((a[8]+b[8])*iv, (a[9]+b[9])*iv);
    r.y = h2pack((a[10]+b[10])*iv, (a[11]+b[11])*iv);
    o[64] = r;
}

// width 10: thread per (node, feature), fp32 source
__global__ void k_gather10(const int* __restrict__ rowptr, const int* __restrict__ csrc,
                           const float* __restrict__ x, float* __restrict__ agg, int n) {
    int idx = blockIdx.x * blockDim.x + threadIdx.x;
    if (idx >= n * IN_DIM) return;
    int node = idx / IN_DIM, f = idx % IN_DIM;
    int beg = rowptr[node], end = rowptr[node + 1];
    float a = 0.0f;
    for (int e = beg; e < end; e++)
        a += x[(size_t)csrc[e] * IN_DIM + f];
    agg[idx] = a / fmaxf((float)(end - beg), 1.0f);
}

// ---------------------------------------------------------------------------
// Layer 0 SAGE: K=10, 32 rows/block, 384 threads; writes fp16 only
// ---------------------------------------------------------------------------
#define L0R 32
__global__ void k_layer0(const float* __restrict__ agg, const float* __restrict__ x,
                         const float* __restrict__ Wl, const float* __restrict__ bl,
                         const float* __restrict__ Wr,
                         const float* __restrict__ bng, const float* __restrict__ bnb,
                         const float* __restrict__ bnm, const float* __restrict__ bnv,
                         __half* __restrict__ hs, int n) {
    __shared__ float sA[L0R][IN_DIM];
    __shared__ float sX[L0R][IN_DIM];
    __shared__ float red[L0R];
    int t = threadIdx.x;
    int row0 = blockIdx.x * L0R;

    if (t < L0R * IN_DIM) {
        int r = t / IN_DIM, k = t % IN_DIM;
        int row = row0 + r;
        sA[r][k] = (row < n) ? agg[(size_t)row * IN_DIM + k] : 0.0f;
        sX[r][k] = (row < n) ? x[(size_t)row * IN_DIM + k] : 0.0f;
    } else if (t < L0R * IN_DIM + L0R) {
        red[t - L0R * IN_DIM] = 0.0f;
    }
    __syncthreads();

    int j = t;
    float wl[IN_DIM], wr[IN_DIM];
#pragma unroll
    for (int k = 0; k < IN_DIM; k++) {
        wl[k] = Wl[j * IN_DIM + k];
        wr[k] = Wr[j * IN_DIM + k];
    }
    float bb = bl[j];

    float v[L0R];
#pragma unroll
    for (int r = 0; r < L0R; r++) {
        float s = bb;
#pragma unroll
        for (int k = 0; k < IN_DIM; k++)
            s += sA[r][k] * wl[k] + sX[r][k] * wr[k];
        v[r] = s;
    }

    int lane = t & 31;
#pragma unroll
    for (int r = 0; r < L0R; r++) {
        float p = v[r] * v[r];
#pragma unroll
        for (int o = 16; o > 0; o >>= 1) p += __shfl_xor_sync(0xFFFFFFFFu, p, o);
        if (lane == 0) atomicAdd(&red[r], p);
    }
    __syncthreads();

    float gm = bng[j], gb = bnb[j], mm = bnm[j], vv = bnv[j];
    float bscale = rsqrtf(vv + BN_EPS) * gm;
#pragma unroll
    for (int r = 0; r < L0R; r++) {
        int row = row0 + r;
        if (row >= n) continue;
        float sc = 1.0f / fmaxf(sqrtf(red[r]), 1e-12f);
        float val = elu_f((v[r] * sc - mm) * bscale + gb);
        hs[(size_t)row * HID + j] = __float2half(val);
    }
}

// ---------------------------------------------------------------------------
// fp16 mma.sync m16n8k16 fused GEMM — proven loop; all-fp16 operands
//   C[64, 384] = A1 * W1^T (+ A2 * W2^T) + bias   (A, W already fp16)
//   epi 0: L2-normalize row, BN, ELU -> fp16 out
//   epi 1: BN, ReLU -> fp16 out
//   epi 2: BN, ReLU, then outf = h @ Wp2^T + bp2 (writes [N,3] fp32)
// ---------------------------------------------------------------------------
#define HSTR 24

__global__ void __launch_bounds__(512, 1)
k_mma(const __half* __restrict__ A1, const __half* __restrict__ W1,
      const float* __restrict__ bias,
      const __half* __restrict__ A2, const __half* __restrict__ W2,
      const float* __restrict__ bng, const float* __restrict__ bnb,
      const float* __restrict__ bnm, const float* __restrict__ bnv,
      __half* __restrict__ outh, float* __restrict__ outf,
      int nrows, int epi,
      const float* __restrict__ Wp2, const float* __restrict__ bp2) {
    __shared__ __half As[64 * HSTR];
    __shared__ __half Ws[384 * HSTR];
    __shared__ float sSB[HID], sS2[HID], sAD[HID];
    __shared__ float sWp[3 * HID];
    __shared__ float red[64];
    __shared__ float redF[192];

    const int tid  = threadIdx.x;
    const int lane = tid & 31;
    const int wid  = tid >> 5;
    const int rw   = wid & 1;
    const int cw   = wid >> 1;
    const int g    = lane >> 2;
    const int t4   = lane & 3;
    const int warpRow = rw * 32;
    const int cb   = cw * 48;
    const int rb   = blockIdx.x * 64;

    for (int c = tid; c < HID; c += 512) {
        float s2 = rsqrtf(bnv[c] + BN_EPS) * bng[c];
        sSB[c] = bias[c];
        sS2[c] = s2;
        sAD[c] = bnb[c] - bnm[c] * s2;
    }
    if (tid < 64) red[tid] = 0.0f;
    if (tid < 192) redF[tid] = 0.0f;
    if (epi == 2)
        for (int c = tid; c < 3 * HID; c += 512) sWp[c] = Wp2[c];
    __syncthreads();

    const int ar = tid >> 2, aq = tid & 3;
    int wr_[3], wq_[3];
#pragma unroll
    for (int i = 0; i < 3; i++) {
        int idx = tid + i * 512;
        wr_[i] = idx >> 2;
        wq_[i] = idx & 3;
    }

    const int npass = (A2 == nullptr) ? 1 : 2;
    const int S = 24 * npass;

    float acc[2][6][4];
#pragma unroll
    for (int mt = 0; mt < 2; mt++)
#pragma unroll
        for (int nt = 0; nt < 6; nt++)
#pragma unroll
            for (int q = 0; q < 4; q++) acc[mt][nt][q] = 0.0f;

    uint2 avP = make_uint2(0u, 0u);
    uint2 wvP[3];

    {
        if (tid < 256) {
            int row = rb + ar;
            if (row < nrows)
                avP = *(const uint2*)(A1 + (size_t)row * HID + aq * 4);
        }
#pragma unroll
        for (int i = 0; i < 3; i++)
            wvP[i] = *(const uint2*)(W1 + (size_t)wr_[i] * HID + wq_[i] * 4);
    }

    for (int it = 0; it < S; it++) {
        // stage to SMEM (pure copy, operands already fp16)
        if (tid < 256)
            *(uint2*)&As[ar * HSTR + aq * 4] = avP;
#pragma unroll
        for (int i = 0; i < 3; i++)
            *(uint2*)&Ws[wr_[i] * HSTR + wq_[i] * 4] = wvP[i];
        __syncthreads();

        // prefetch next chunk
        if (it + 1 < S) {
            const int itn = it + 1;
            const int pass = itn / 24;
            const int k0 = (itn % 24) * 16;
            const __half* A = pass ? A2 : A1;
            const __half* W = pass ? W2 : W1;
            if (tid < 256) {
                int row = rb + ar;
                avP = make_uint2(0u, 0u);
                if (row < nrows)
                    avP = *(const uint2*)(A + (size_t)row * HID + k0 + aq * 4);
            }
#pragma unroll
            for (int i = 0; i < 3; i++)
                wvP[i] = *(const uint2*)(W + (size_t)wr_[i] * HID + k0 + wq_[i] * 4);
        }

        // compute: one k16 step, 12 MMAs
        {
            uint32_t a[2][4];
#pragma unroll
            for (int mt = 0; mt < 2; mt++) {
                int r0 = warpRow + mt * 16 + g;
                a[mt][0] = *(uint32_t*)&As[r0 * HSTR + t4 * 2];
                a[mt][1] = *(uint32_t*)&As[(r0 + 8) * HSTR + t4 * 2];
                a[mt][2] = *(uint32_t*)&As[r0 * HSTR + t4 * 2 + 8];
                a[mt][3] = *(uint32_t*)&As[(r0 + 8) * HSTR + t4 * 2 + 8];
            }
#pragma unroll
            for (int nt = 0; nt < 6; nt++) {
                int n0 = cb + nt * 8 + g;
                uint32_t b0 = *(uint32_t*)&Ws[n0 * HSTR + t4 * 2];
                uint32_t b1 = *(uint32_t*)&Ws[n0 * HSTR + t4 * 2 + 8];
                mma_f16(acc[0][nt], a[0][0], a[0][1], a[0][2], a[0][3], b0, b1);
                mma_f16(acc[1][nt], a[1][0], a[1][1], a[1][2], a[1][3], b0, b1);
            }
        }
        __syncthreads();
    }

    // ---- epilogue ----
#pragma unroll
    for (int nt = 0; nt < 6; nt++) {
        int col = cb + nt * 8 + 2 * t4;
        float b0 = sSB[col], b1 = sSB[col + 1];
#pragma unroll
        for (int mt = 0; mt < 2; mt++) {
            acc[mt][nt][0] += b0; acc[mt][nt][1] += b1;
            acc[mt][nt][2] += b0; acc[mt][nt][3] += b1;
        }
    }

    float sc0[2] = {1.0f, 1.0f}, sc1[2] = {1.0f, 1.0f};
    if (epi == 0) {
#pragma unroll
        for (int mt = 0; mt < 2; mt++) {
            float s0 = 0.0f, s1 = 0.0f;
#pragma unroll
            for (int nt = 0; nt < 6; nt++) {
                s0 = fmaf(acc[mt][nt][0], acc[mt][nt][0], s0);
                s0 = fmaf(acc[mt][nt][1], acc[mt][nt][1], s0);
                s1 = fmaf(acc[mt][nt][2], acc[mt][nt][2], s1);
                s1 = fmaf(acc[mt][nt][3], acc[mt][nt][3], s1);
            }
            s0 += __shfl_xor_sync(0xFFFFFFFFu, s0, 1);
            s0 += __shfl_xor_sync(0xFFFFFFFFu, s0, 2);
            s1 += __shfl_xor_sync(0xFFFFFFFFu, s1, 1);
            s1 += __shfl_xor_sync(0xFFFFFFFFu, s1, 2);
            if (t4 == 0) {
                atomicAdd(&red[warpRow + mt * 16 + g], s0);
                atomicAdd(&red[warpRow + mt * 16 + g + 8], s1);
            }
        }
        __syncthreads();
#pragma unroll
        for (int mt = 0; mt < 2; mt++) {
            sc0[mt] = 1.0f / fmaxf(sqrtf(red[warpRow + mt * 16 + g]), 1e-12f);
            sc1[mt] = 1.0f / fmaxf(sqrtf(red[warpRow + mt * 16 + g + 8]), 1e-12f);
        }
    }

    if (epi == 2) {
        float p0[2][3], p1[2][3];
#pragma unroll
        for (int mt = 0; mt < 2; mt++)
#pragma unroll
            for (int o = 0; o < 3; o++) { p0[mt][o] = 0.0f; p1[mt][o] = 0.0f; }

#pragma unroll
        for (int mt = 0; mt < 2; mt++) {
#pragma unroll
            for (int nt = 0; nt < 6; nt++) {
                int col = cb + nt * 8 + 2 * t4;
                float m0 = sS2[col], m1 = sS2[col + 1];
                float d0 = sAD[col], d1 = sAD[col + 1];
                float x0 = fmaxf(acc[mt][nt][0] * m0 + d0, 0.0f);
                float x1 = fmaxf(acc[mt][nt][1] * m1 + d1, 0.0f);
                float x2 = fmaxf(acc[mt][nt][2] * m0 + d0, 0.0f);
                float x3 = fmaxf(acc[mt][nt][3] * m1 + d1, 0.0f);
#pragma unroll
                for (int o = 0; o < 3; o++) {
                    float w0 = sWp[o * HID + col], w1 = sWp[o * HID + col + 1];
                    p0[mt][o] = fmaf(x0, w0, fmaf(x1, w1, p0[mt][o]));
                    p1[mt][o] = fmaf(x2, w0, fmaf(x3, w1, p1[mt][o]));
                }
            }
        }
#pragma unroll
        for (int mt = 0; mt < 2; mt++)
#pragma unroll
            for (int o = 0; o < 3; o++) {
                float v0 = p0[mt][o], v1 = p1[mt][o];
                v0 += __shfl_xor_sync(0xFFFFFFFFu, v0, 1);
                v0 += __shfl_xor_sync(0xFFFFFFFFu, v0, 2);
                v1 += __shfl_xor_sync(0xFFFFFFFFu, v1, 1);
                v1 += __shfl_xor_sync(0xFFFFFFFFu, v1, 2);
                if (t4 == 0) {
                    atomicAdd(&redF[(warpRow + mt * 16 + g) * 3 + o], v0);
                    atomicAdd(&redF[(warpRow + mt * 16 + g + 8) * 3 + o], v1);
                }
            }
        __syncthreads();
        if (tid < 64) {
            int row = rb + tid;
            if (row < nrows) {
                outf[(size_t)row * 3 + 0] = redF[tid * 3 + 0] + bp2[0];
                outf[(size_t)row * 3 + 1] = redF[tid * 3 + 1] + bp2[1];
                outf[(size_t)row * 3 + 2] = redF[tid * 3 + 2] + bp2[2];
            }
        }
        return;
    }

#pragma unroll
    for (int mt = 0; mt < 2; mt++) {
        int row0 = rb + warpRow + mt * 16 + g;
        int row1 = row0 + 8;
        bool v0r = (row0 < nrows), v1r = (row1 < nrows);
#pragma unroll
        for (int nt = 0; nt < 6; nt++) {
            int col = cb + nt * 8 + 2 * t4;
            float m0 = sS2[col], m1 = sS2[col + 1];
            float d0 = sAD[col], d1 = sAD[col + 1];
            float x0 = acc[mt][nt][0] * sc0[mt] * m0 + d0;
            float x1 = acc[mt][nt][1] * sc0[mt] * m1 + d1;
            float x2 = acc[mt][nt][2] * sc1[mt] * m0 + d0;
            float x3 = acc[mt][nt][3] * sc1[mt] * m1 + d1;
            if (epi == 0) {
                x0 = elu_f(x0); x1 = elu_f(x1);
                x2 = elu_f(x2); x3 = elu_f(x3);
            } else {
                x0 = fmaxf(x0, 0.0f); x1 = fmaxf(x1, 0.0f);
                x2 = fmaxf(x2, 0.0f); x3 = fmaxf(x3, 0.0f);
            }
            if (v0r) *(uint32_t*)(outh + (size_t)row0 * HID + col) = h2pack(x0, x1);
            if (v1r) *(uint32_t*)(outh + (size_t)row1 * HID + col) = h2pack(x2, x3);
        }
    }
}

// ---------------------------------------------------------------------------
extern "C" void kernel_launch(void* const* d_in, const int* in_sizes, int n_in,
                              void* d_out, int out_size) {
    const float* x    = (const float*)d_in[0];
    const int*   ei   = (const int*)  d_in[1];
    const float* Wl0  = (const float*)d_in[2];
    const float* bl0  = (const float*)d_in[3];
    const float* Wr0  = (const float*)d_in[4];
    const float* Wl   = (const float*)d_in[5];
    const float* bl   = (const float*)d_in[6];
    const float* Wr   = (const float*)d_in[7];
    const float* bng  = (const float*)d_in[8];
    const float* bnb  = (const float*)d_in[9];
    const float* bnm  = (const float*)d_in[10];
    const float* bnv  = (const float*)d_in[11];
    const float* Wp0  = (const float*)d_in[12];
    const float* bp0  = (const float*)d_in[13];
    const float* Wp1  = (const float*)d_in[14];
    const float* bp1  = (const float*)d_in[15];
    const float* Wp2  = (const float*)d_in[16];
    const float* bp2  = (const float*)d_in[17];
    const float* pg   = (const float*)d_in[18];
    const float* pb   = (const float*)d_in[19];
    const float* pm   = (const float*)d_in[20];
    const float* pv   = (const float*)d_in[21];

    const int* src = ei;
    const int* dst = ei + EE;

    __half *agg16, *shA, *shB, *wl16, *wr16, *wp016, *wp116;
    float *agg10;
    int *deg, *inc, *rowptr, *cur, *csrc, *bsum;
    cudaGetSymbolAddress((void**)&agg16,  g_agg16);
    cudaGetSymbolAddress((void**)&shA,    g_shA);
    cudaGetSymbolAddress((void**)&shB,    g_shB);
    cudaGetSymbolAddress((void**)&agg10,  g_agg10);
    cudaGetSymbolAddress((void**)&wl16,   g_wl16);
    cudaGetSymbolAddress((void**)&wr16,   g_wr16);
    cudaGetSymbolAddress((void**)&wp016,  g_wp016);
    cudaGetSymbolAddress((void**)&wp116,  g_wp116);
    cudaGetSymbolAddress((void**)&deg,    g_deg);
    cudaGetSymbolAddress((void**)&inc,    g_inc);
    cudaGetSymbolAddress((void**)&rowptr, g_rowptr);
    cudaGetSymbolAddress((void**)&cur,    g_cur);
    cudaGetSymbolAddress((void**)&csrc,   g_csrc);
    cudaGetSymbolAddress((void**)&bsum,   g_bsum);

    // ---- weight conversion (fp32 -> fp16), once per call ----
    {
        int n4 = 4 * WMAT / 4;
        k_cvt4<<<(n4 + 255) / 256, 256>>>((const float4*)Wl, (uint2*)wl16, n4);
        k_cvt4<<<(n4 + 255) / 256, 256>>>((const float4*)Wr, (uint2*)wr16, n4);
        int p4 = WMAT / 4;
        k_cvt4<<<(p4 + 255) / 256, 256>>>((const float4*)Wp0, (uint2*)wp016, p4);
        k_cvt4<<<(p4 + 255) / 256, 256>>>((const float4*)Wp1, (uint2*)wp116, p4);
    }

    // ---- CSR build ----
    cudaMemsetAsync(deg, 0, NN * sizeof(int));
    k_hist<<<(EE + 255) / 256, 256>>>(dst, deg, EE);
    k_scan_block<<<NSCANB, SCAN_B>>>(deg, inc, bsum, NN);
    k_scan_bsum<<<1, 128>>>(bsum, NSCANB);
    k_csr_fin<<<(NN + 255) / 256, 256>>>(deg, inc, bsum, rowptr, cur, NN);
    k_fill<<<(EE + 255) / 256, 256>>>(src, dst, cur, csrc, EE);

    // ---- layer 0 (K=10) ----
    k_gather10<<<(NN * IN_DIM + 255) / 256, 256>>>(rowptr, csrc, x, agg10, NN);
    k_layer0<<<(NN + L0R - 1) / L0R, 384>>>(agg10, x, Wl0, bl0, Wr0,
                                            bng, bnb, bnm, bnv, shA, NN);

    // ---- layers 1..4: fp16 gather + dual fp16 mma GEMM ----
    const int gblocks = (NN + 63) / 64;
    for (int t = 1; t < TT; t++) {
        k_gather384<<<(NN * 32 + 255) / 256, 256>>>(rowptr, csrc, shA, agg16, NN);
        k_mma<<<gblocks, 512>>>(
            agg16, wl16 + (size_t)(t - 1) * WMAT, bl + (t - 1) * HID,
            shA,   wr16 + (size_t)(t - 1) * WMAT,
            bng + t * HID, bnb + t * HID, bnm + t * HID, bnv + t * HID,
            shB, nullptr, NN, 0, nullptr, nullptr);
        __half* ts = shA; shA = shB; shB = ts;
    }

    // ---- projection MLP (final [384->3] fused into second GEMM) ----
    k_mma<<<gblocks, 512>>>(shA, wp016, bp0, nullptr, nullptr,
                            pg, pb, pm, pv, shB, nullptr, NN, 1,
                            nullptr, nullptr);
    k_mma<<<gblocks, 512>>>(shB, wp116, bp1, nullptr, nullptr,
                            pg + HID, pb + HID, pm + HID, pv + HID,
                            nullptr, (float*)d_out, NN, 2,
                            Wp2, bp2);

    (void)in_sizes; (void)n_in; (void)out_size;
}

// round 10
// speedup vs baseline: 1.7890x; 1.0545x over previous
#include <cuda_runtime.h>
#include <cuda_fp16.h>
#include <math.h>
#include <cstdint>

#define NN 100000
#define EE 300000
#define IN_DIM 10
#define HID 384
#define TT 5
#define BN_EPS 1e-5f
#define WMAT (HID * HID)

#define SCAN_B 1024
#define NSCANB ((NN + SCAN_B - 1) / SCAN_B)   // 98

// Static scratch (allocation-free rule) — all activations fp16
__device__ __half  g_agg16[(size_t)NN * HID];
__device__ __half  g_shA [(size_t)NN * HID];
__device__ __half  g_shB [(size_t)NN * HID];
__device__ float   g_agg10[(size_t)NN * IN_DIM];
__device__ __half  g_wl16[4 * WMAT];
__device__ __half  g_wr16[4 * WMAT];
__device__ __half  g_wp016[WMAT];
__device__ __half  g_wp116[WMAT];
__device__ int   g_deg [NN];
__device__ int   g_inc [NN];
__device__ int   g_rowptr[NN + 1];
__device__ int   g_cur [NN];
__device__ int   g_csrc[EE];
__device__ int   g_bsum[128];

// ---------------------------------------------------------------------------
// helpers
// ---------------------------------------------------------------------------
__device__ __forceinline__ uint32_t smem_u32(const void* p) {
    uint32_t a;
    asm("{ .reg .u64 t; cvta.to.shared.u64 t, %1; cvt.u32.u64 %0, t; }" : "=r"(a) : "l"(p));
    return a;
}

__device__ __forceinline__ void mma_f16(float* c, uint32_t a0, uint32_t a1,
                                        uint32_t a2, uint32_t a3,
                                        uint32_t b0, uint32_t b1) {
    asm volatile("mma.sync.aligned.m16n8k16.row.col.f32.f16.f16.f32 "
                 "{%0,%1,%2,%3}, {%4,%5,%6,%7}, {%8,%9}, {%0,%1,%2,%3};"
                 : "+f"(c[0]), "+f"(c[1]), "+f"(c[2]), "+f"(c[3])
                 : "r"(a0), "r"(a1), "r"(a2), "r"(a3), "r"(b0), "r"(b1));
}

#define LDSM_X4(r0, r1, r2, r3, addr) \
    asm volatile("ldmatrix.sync.aligned.m8n8.x4.shared.b16 {%0,%1,%2,%3}, [%4];" \
                 : "=r"(r0), "=r"(r1), "=r"(r2), "=r"(r3) : "r"(addr))

__device__ __forceinline__ float elu_f(float v) {
    return (v > 0.0f) ? v : (__expf(v) - 1.0f);
}

__device__ __forceinline__ uint32_t h2pack(float x, float y) {
    __half2 h = __float22half2_rn(make_float2(x, y));
    return *(uint32_t*)&h;
}

// fp32 -> fp16 weight conversion (vectorized)
__global__ void k_cvt4(const float4* __restrict__ src, uint2* __restrict__ dst, int n4) {
    int i = blockIdx.x * blockDim.x + threadIdx.x;
    if (i >= n4) return;
    float4 v = src[i];
    uint2 o;
    o.x = h2pack(v.x, v.y);
    o.y = h2pack(v.z, v.w);
    dst[i] = o;
}

// ---------------------------------------------------------------------------
// CSR build
// ---------------------------------------------------------------------------
__global__ void k_hist(const int* __restrict__ dst, int* __restrict__ deg, int e) {
    int i = blockIdx.x * blockDim.x + threadIdx.x;
    if (i < e) atomicAdd(&deg[dst[i]], 1);
}

__global__ void k_scan_block(const int* __restrict__ deg, int* __restrict__ inc,
                             int* __restrict__ bsum, int n) {
    __shared__ int s[SCAN_B];
    int i = blockIdx.x * SCAN_B + threadIdx.x;
    s[threadIdx.x] = (i < n) ? deg[i] : 0;
    __syncthreads();
#pragma unroll
    for (int o = 1; o < SCAN_B; o <<= 1) {
        int t = (threadIdx.x >= o) ? s[threadIdx.x - o] : 0;
        __syncthreads();
        s[threadIdx.x] += t;
        __syncthreads();
    }
    if (i < n) inc[i] = s[threadIdx.x];
    if (threadIdx.x == SCAN_B - 1) bsum[blockIdx.x] = s[SCAN_B - 1];
}

__global__ void k_scan_bsum(int* __restrict__ bsum, int nb) {
    __shared__ int s[128];
    if (threadIdx.x < nb) s[threadIdx.x] = bsum[threadIdx.x];
    __syncthreads();
    if (threadIdx.x == 0) {
        int run = 0;
        for (int i = 0; i < nb; i++) { run += s[i]; s[i] = run; }
    }
    __syncthreads();
    if (threadIdx.x < nb) bsum[threadIdx.x] = s[threadIdx.x];
}

__global__ void k_csr_fin(const int* __restrict__ deg, const int* __restrict__ inc,
                          const int* __restrict__ bsum,
                          int* __restrict__ rowptr, int* __restrict__ cur, int n) {
    int i = blockIdx.x * blockDim.x + threadIdx.x;
    if (i >= n) return;
    int b = i / SCAN_B;
    int total = inc[i] + (b > 0 ? bsum[b - 1] : 0);
    rowptr[i + 1] = total;
    cur[i] = total - deg[i];
    if (i == 0) rowptr[0] = 0;
}

__global__ void k_fill(const int* __restrict__ src, const int* __restrict__ dst,
                       int* __restrict__ cur, int* __restrict__ csrc, int e) {
    int i = blockIdx.x * blockDim.x + threadIdx.x;
    if (i >= e) return;
    int pos = atomicAdd(&cur[dst[i]], 1);
    csrc[pos] = src[i];
}

// ---------------------------------------------------------------------------
// CSR mean-gather, width 384, fp16 in/out, fp32 accumulate, 2x unroll
// ---------------------------------------------------------------------------
__global__ void k_gather384(const int* __restrict__ rowptr, const int* __restrict__ csrc,
                            const __half* __restrict__ hs, __half* __restrict__ agg,
                            int n) {
    int node = (blockIdx.x * blockDim.x + threadIdx.x) >> 5;
    int lane = threadIdx.x & 31;
    if (node >= n) return;
    int beg = rowptr[node], end = rowptr[node + 1];
    float a[12], b[12];
#pragma unroll
    for (int i = 0; i < 12; i++) { a[i] = 0.0f; b[i] = 0.0f; }

    int e = beg;
    for (; e + 1 < end; e += 2) {
        int s0 = csrc[e], s1 = csrc[e + 1];
        const uint2* p0 = (const uint2*)(hs + (size_t)s0 * HID) + lane;
        const uint2* p1 = (const uint2*)(hs + (size_t)s1 * HID) + lane;
        uint2 u0 = p0[0], u1 = p0[32], u2 = p0[64];
        uint2 w0 = p1[0], w1 = p1[32], w2 = p1[64];
        float2 f;
        f = __half22float2(*(__half2*)&u0.x); a[0] += f.x; a[1] += f.y;
        f = __half22float2(*(__half2*)&u0.y); a[2] += f.x; a[3] += f.y;
        f = __half22float2(*(__half2*)&u1.x); a[4] += f.x; a[5] += f.y;
        f = __half22float2(*(__half2*)&u1.y); a[6] += f.x; a[7] += f.y;
        f = __half22float2(*(__half2*)&u2.x); a[8] += f.x; a[9] += f.y;
        f = __half22float2(*(__half2*)&u2.y); a[10] += f.x; a[11] += f.y;
        f = __half22float2(*(__half2*)&w0.x); b[0] += f.x; b[1] += f.y;
        f = __half22float2(*(__half2*)&w0.y); b[2] += f.x; b[3] += f.y;
        f = __half22float2(*(__half2*)&w1.x); b[4] += f.x; b[5] += f.y;
        f = __half22float2(*(__half2*)&w1.y); b[6] += f.x; b[7] += f.y;
        f = __half22float2(*(__half2*)&w2.x); b[8] += f.x; b[9] += f.y;
        f = __half22float2(*(__half2*)&w2.y); b[10] += f.x; b[11] += f.y;
    }
    if (e < end) {
        const uint2* p0 = (const uint2*)(hs + (size_t)csrc[e] * HID) + lane;
        uint2 u0 = p0[0], u1 = p0[32], u2 = p0[64];
        float2 f;
        f = __half22float2(*(__half2*)&u0.x); a[0] += f.x; a[1] += f.y;
        f = __half22float2(*(__half2*)&u0.y); a[2] += f.x; a[3] += f.y;
        f = __half22float2(*(__half2*)&u1.x); a[4] += f.x; a[5] += f.y;
        f = __half22float2(*(__half2*)&u1.y); a[6] += f.x; a[7] += f.y;
        f = __half22float2(*(__half2*)&u2.x); a[8] += f.x; a[9] += f.y;
        f = __half22float2(*(__half2*)&u2.y); a[10] += f.x; a[11] += f.y;
    }

    float iv = 1.0f / fmaxf((float)(end - beg), 1.0f);
    uint2* o = (uint2*)(agg + (size_t)node * HID) + lane;
    uint2 r;
    r.x = h2pack((a[0]+b[0])*iv, (a[1]+b[1])*iv);
    r.y = h2pack((a[2]+b[2])*iv, (a[3]+b[3])*iv);
    o[0] = r;
    r.x = h2pack((a[4]+b[4])*iv, (a[5]+b[5])*iv);
    r.y = h2pack((a[6]+b[6])*iv, (a[7]+b[7])*iv);
    o[32] = r;
    r.x = h2pack((a[8]+b[8])*iv, (a[9]+b[9])*iv);
    r.y = h2pack((a[10]+b[10])*iv, (a[11]+b[11])*iv);
    o[64] = r;
}

// width 10: thread per (node, feature), fp32 source
__global__ void k_gather10(const int* __restrict__ rowptr, const int* __restrict__ csrc,
                           const float* __restrict__ x, float* __restrict__ agg, int n) {
    int idx = blockIdx.x * blockDim.x + threadIdx.x;
    if (idx >= n * IN_DIM) return;
    int node = idx / IN_DIM, f = idx % IN_DIM;
    int beg = rowptr[node], end = rowptr[node + 1];
    float a = 0.0f;
    for (int e = beg; e < end; e++)
        a += x[(size_t)csrc[e] * IN_DIM + f];
    agg[idx] = a / fmaxf((float)(end - beg), 1.0f);
}

// ---------------------------------------------------------------------------
// Layer 0 SAGE: K=10, 32 rows/block, 384 threads; writes fp16 only
// ---------------------------------------------------------------------------
#define L0R 32
__global__ void k_layer0(const float* __restrict__ agg, const float* __restrict__ x,
                         const float* __restrict__ Wl, const float* __restrict__ bl,
                         const float* __restrict__ Wr,
                         const float* __restrict__ bng, const float* __restrict__ bnb,
                         const float* __restrict__ bnm, const float* __restrict__ bnv,
                         __half* __restrict__ hs, int n) {
    __shared__ float sA[L0R][IN_DIM];
    __shared__ float sX[L0R][IN_DIM];
    __shared__ float red[L0R];
    int t = threadIdx.x;
    int row0 = blockIdx.x * L0R;

    if (t < L0R * IN_DIM) {
        int r = t / IN_DIM, k = t % IN_DIM;
        int row = row0 + r;
        sA[r][k] = (row < n) ? agg[(size_t)row * IN_DIM + k] : 0.0f;
        sX[r][k] = (row < n) ? x[(size_t)row * IN_DIM + k] : 0.0f;
    } else if (t < L0R * IN_DIM + L0R) {
        red[t - L0R * IN_DIM] = 0.0f;
    }
    __syncthreads();

    int j = t;
    float wl[IN_DIM], wr[IN_DIM];
#pragma unroll
    for (int k = 0; k < IN_DIM; k++) {
        wl[k] = Wl[j * IN_DIM + k];
        wr[k] = Wr[j * IN_DIM + k];
    }
    float bb = bl[j];

    float v[L0R];
#pragma unroll
    for (int r = 0; r < L0R; r++) {
        float s = bb;
#pragma unroll
        for (int k = 0; k < IN_DIM; k++)
            s += sA[r][k] * wl[k] + sX[r][k] * wr[k];
        v[r] = s;
    }

    int lane = t & 31;
#pragma unroll
    for (int r = 0; r < L0R; r++) {
        float p = v[r] * v[r];
#pragma unroll
        for (int o = 16; o > 0; o >>= 1) p += __shfl_xor_sync(0xFFFFFFFFu, p, o);
        if (lane == 0) atomicAdd(&red[r], p);
    }
    __syncthreads();

    float gm = bng[j], gb = bnb[j], mm = bnm[j], vv = bnv[j];
    float bscale = rsqrtf(vv + BN_EPS) * gm;
#pragma unroll
    for (int r = 0; r < L0R; r++) {
        int row = row0 + r;
        if (row >= n) continue;
        float sc = 1.0f / fmaxf(sqrtf(red[r]), 1e-12f);
        float val = elu_f((v[r] * sc - mm) * bscale + gb);
        hs[(size_t)row * HID + j] = __float2half(val);
    }
}

// ---------------------------------------------------------------------------
// fp16 mma.sync m16n8k16 fused GEMM — ldmatrix fragment loads
//   C[64, 384] = A1 * W1^T (+ A2 * W2^T) + bias   (A, W fp16)
//   epi 0: L2-normalize row, BN, ELU -> fp16 out
//   epi 1: BN, ReLU -> fp16 out
//   epi 2: BN, ReLU, then outf = h @ Wp2^T + bp2 (writes [N,3] fp32)
// ---------------------------------------------------------------------------
#define HSTR 24

__global__ void __launch_bounds__(512, 1)
k_mma(const __half* __restrict__ A1, const __half* __restrict__ W1,
      const float* __restrict__ bias,
      const __half* __restrict__ A2, const __half* __restrict__ W2,
      const float* __restrict__ bng, const float* __restrict__ bnb,
      const float* __restrict__ bnm, const float* __restrict__ bnv,
      __half* __restrict__ outh, float* __restrict__ outf,
      int nrows, int epi,
      const float* __restrict__ Wp2, const float* __restrict__ bp2) {
    __shared__ __half As[64 * HSTR];
    __shared__ __half Ws[384 * HSTR];
    __shared__ float sSB[HID], sS2[HID], sAD[HID];
    __shared__ float sWp[3 * HID];
    __shared__ float red[64];
    __shared__ float redF[192];

    const int tid  = threadIdx.x;
    const int lane = tid & 31;
    const int wid  = tid >> 5;
    const int rw   = wid & 1;
    const int cw   = wid >> 1;
    const int g    = lane >> 2;
    const int t4   = lane & 3;
    const int warpRow = rw * 32;
    const int cb   = cw * 48;
    const int rb   = blockIdx.x * 64;

    for (int c = tid; c < HID; c += 512) {
        float s2 = rsqrtf(bnv[c] + BN_EPS) * bng[c];
        sSB[c] = bias[c];
        sS2[c] = s2;
        sAD[c] = bnb[c] - bnm[c] * s2;
    }
    if (tid < 64) red[tid] = 0.0f;
    if (tid < 192) redF[tid] = 0.0f;
    if (epi == 2)
        for (int c = tid; c < 3 * HID; c += 512) sWp[c] = Wp2[c];
    __syncthreads();

    // ldmatrix lane addresses (loop-invariant, single buffer)
    // m = lane>>3 selects the 8x8 matrix within .x4
    const int m8 = lane >> 3;
    const int r8 = lane & 7;
    uint32_t aAddr[2], bAddr[3];
    {
        int rowi = (m8 & 1) * 8 + r8;      // A: matrices {r0-7,k0}, {r8-15,k0}, {r0-7,k8}, {r8-15,k8}
        int koff = (m8 >> 1) * 8;
#pragma unroll
        for (int mt = 0; mt < 2; mt++)
            aAddr[mt] = smem_u32(&As[(warpRow + mt * 16 + rowi) * HSTR + koff]);
        int nrowi = (m8 >> 1) * 8 + r8;    // B: matrices {n0-7,k0}, {n0-7,k8}, {n8-15,k0}, {n8-15,k8}
        int nkoff = (m8 & 1) * 8;
#pragma unroll
        for (int p = 0; p < 3; p++)
            bAddr[p] = smem_u32(&Ws[(cb + p * 16 + nrowi) * HSTR + nkoff]);
    }

    const int ar = tid >> 2, aq = tid & 3;
    int wr_[3], wq_[3];
#pragma unroll
    for (int i = 0; i < 3; i++) {
        int idx = tid + i * 512;
        wr_[i] = idx >> 2;
        wq_[i] = idx & 3;
    }

    const int npass = (A2 == nullptr) ? 1 : 2;
    const int S = 24 * npass;

    float acc[2][6][4];
#pragma unroll
    for (int mt = 0; mt < 2; mt++)
#pragma unroll
        for (int nt = 0; nt < 6; nt++)
#pragma unroll
            for (int q = 0; q < 4; q++) acc[mt][nt][q] = 0.0f;

    uint2 avP = make_uint2(0u, 0u);
    uint2 wvP[3];

    {
        if (tid < 256) {
            int row = rb + ar;
            if (row < nrows)
                avP = *(const uint2*)(A1 + (size_t)row * HID + aq * 4);
        }
#pragma unroll
        for (int i = 0; i < 3; i++)
            wvP[i] = *(const uint2*)(W1 + (size_t)wr_[i] * HID + wq_[i] * 4);
    }

    for (int it = 0; it < S; it++) {
        // stage to SMEM (pure copy)
        if (tid < 256)
            *(uint2*)&As[ar * HSTR + aq * 4] = avP;
#pragma unroll
        for (int i = 0; i < 3; i++)
            *(uint2*)&Ws[wr_[i] * HSTR + wq_[i] * 4] = wvP[i];
        __syncthreads();

        // prefetch next chunk
        if (it + 1 < S) {
            const int itn = it + 1;
            const int pass = itn / 24;
            const int k0 = (itn % 24) * 16;
            const __half* A = pass ? A2 : A1;
            const __half* W = pass ? W2 : W1;
            if (tid < 256) {
                int row = rb + ar;
                avP = make_uint2(0u, 0u);
                if (row < nrows)
                    avP = *(const uint2*)(A + (size_t)row * HID + k0 + aq * 4);
            }
#pragma unroll
            for (int i = 0; i < 3; i++)
                wvP[i] = *(const uint2*)(W + (size_t)wr_[i] * HID + k0 + wq_[i] * 4);
        }

        // compute: 5x ldmatrix.x4 + 12 MMAs
        {
            uint32_t a[2][4];
            LDSM_X4(a[0][0], a[0][1], a[0][2], a[0][3], aAddr[0]);
            LDSM_X4(a[1][0], a[1][1], a[1][2], a[1][3], aAddr[1]);
            uint32_t bfr[12];
            LDSM_X4(bfr[0], bfr[1], bfr[2],  bfr[3],  bAddr[0]);
            LDSM_X4(bfr[4], bfr[5], bfr[6],  bfr[7],  bAddr[1]);
            LDSM_X4(bfr[8], bfr[9], bfr[10], bfr[11], bAddr[2]);
#pragma unroll
            for (int nt = 0; nt < 6; nt++) {
                uint32_t b0 = bfr[nt * 2], b1 = bfr[nt * 2 + 1];
                mma_f16(acc[0][nt], a[0][0], a[0][1], a[0][2], a[0][3], b0, b1);
                mma_f16(acc[1][nt], a[1][0], a[1][1], a[1][2], a[1][3], b0, b1);
            }
        }
        __syncthreads();
    }

    // ---- epilogue ----
#pragma unroll
    for (int nt = 0; nt < 6; nt++) {
        int col = cb + nt * 8 + 2 * t4;
        float b0 = sSB[col], b1 = sSB[col + 1];
#pragma unroll
        for (int mt = 0; mt < 2; mt++) {
            acc[mt][nt][0] += b0; acc[mt][nt][1] += b1;
            acc[mt][nt][2] += b0; acc[mt][nt][3] += b1;
        }
    }

    float sc0[2] = {1.0f, 1.0f}, sc1[2] = {1.0f, 1.0f};
    if (epi == 0) {
#pragma unroll
        for (int mt = 0; mt < 2; mt++) {
            float s0 = 0.0f, s1 = 0.0f;
#pragma unroll
            for (int nt = 0; nt < 6; nt++) {
                s0 = fmaf(acc[mt][nt][0], acc[mt][nt][0], s0);
                s0 = fmaf(acc[mt][nt][1], acc[mt][nt][1], s0);
                s1 = fmaf(acc[mt][nt][2], acc[mt][nt][2], s1);
                s1 = fmaf(acc[mt][nt][3], acc[mt][nt][3], s1);
            }
            s0 += __shfl_xor_sync(0xFFFFFFFFu, s0, 1);
            s0 += __shfl_xor_sync(0xFFFFFFFFu, s0, 2);
            s1 += __shfl_xor_sync(0xFFFFFFFFu, s1, 1);
            s1 += __shfl_xor_sync(0xFFFFFFFFu, s1, 2);
            if (t4 == 0) {
                atomicAdd(&red[warpRow + mt * 16 + g], s0);
                atomicAdd(&red[warpRow + mt * 16 + g + 8], s1);
            }
        }
        __syncthreads();
#pragma unroll
        for (int mt = 0; mt < 2; mt++) {
            sc0[mt] = 1.0f / fmaxf(sqrtf(red[warpRow + mt * 16 + g]), 1e-12f);
            sc1[mt] = 1.0f / fmaxf(sqrtf(red[warpRow + mt * 16 + g + 8]), 1e-12f);
        }
    }

    if (epi == 2) {
        float p0[2][3], p1[2][3];
#pragma unroll
        for (int mt = 0; mt < 2; mt++)
#pragma unroll
            for (int o = 0; o < 3; o++) { p0[mt][o] = 0.0f; p1[mt][o] = 0.0f; }

#pragma unroll
        for (int mt = 0; mt < 2; mt++) {
#pragma unroll
            for (int nt = 0; nt < 6; nt++) {
                int col = cb + nt * 8 + 2 * t4;
                float m0 = sS2[col], m1 = sS2[col + 1];
                float d0 = sAD[col], d1 = sAD[col + 1];
                float x0 = fmaxf(acc[mt][nt][0] * m0 + d0, 0.0f);
                float x1 = fmaxf(acc[mt][nt][1] * m1 + d1, 0.0f);
                float x2 = fmaxf(acc[mt][nt][2] * m0 + d0, 0.0f);
                float x3 = fmaxf(acc[mt][nt][3] * m1 + d1, 0.0f);
#pragma unroll
                for (int o = 0; o < 3; o++) {
                    float w0 = sWp[o * HID + col], w1 = sWp[o * HID + col + 1];
                    p0[mt][o] = fmaf(x0, w0, fmaf(x1, w1, p0[mt][o]));
                    p1[mt][o] = fmaf(x2, w0, fmaf(x3, w1, p1[mt][o]));
                }
            }
        }
#pragma unroll
        for (int mt = 0; mt < 2; mt++)
#pragma unroll
            for (int o = 0; o < 3; o++) {
                float v0 = p0[mt][o], v1 = p1[mt][o];
                v0 += __shfl_xor_sync(0xFFFFFFFFu, v0, 1);
                v0 += __shfl_xor_sync(0xFFFFFFFFu, v0, 2);
                v1 += __shfl_xor_sync(0xFFFFFFFFu, v1, 1);
                v1 += __shfl_xor_sync(0xFFFFFFFFu, v1, 2);
                if (t4 == 0) {
                    atomicAdd(&redF[(warpRow + mt * 16 + g) * 3 + o], v0);
                    atomicAdd(&redF[(warpRow + mt * 16 + g + 8) * 3 + o], v1);
                }
            }
        __syncthreads();
        if (tid < 64) {
            int row = rb + tid;
            if (row < nrows) {
                outf[(size_t)row * 3 + 0] = redF[tid * 3 + 0] + bp2[0];
                outf[(size_t)row * 3 + 1] = redF[tid * 3 + 1] + bp2[1];
                outf[(size_t)row * 3 + 2] = redF[tid * 3 + 2] + bp2[2];
            }
        }
        return;
    }

#pragma unroll
    for (int mt = 0; mt < 2; mt++) {
        int row0 = rb + warpRow + mt * 16 + g;
        int row1 = row0 + 8;
        bool v0r = (row0 < nrows), v1r = (row1 < nrows);
#pragma unroll
        for (int nt = 0; nt < 6; nt++) {
            int col = cb + nt * 8 + 2 * t4;
            float m0 = sS2[col], m1 = sS2[col + 1];
            float d0 = sAD[col], d1 = sAD[col + 1];
            float x0 = acc[mt][nt][0] * sc0[mt] * m0 + d0;
            float x1 = acc[mt][nt][1] * sc0[mt] * m1 + d1;
            float x2 = acc[mt][nt][2] * sc1[mt] * m0 + d0;
            float x3 = acc[mt][nt][3] * sc1[mt] * m1 + d1;
            if (epi == 0) {
                x0 = elu_f(x0); x1 = elu_f(x1);
                x2 = elu_f(x2); x3 = elu_f(x3);
            } else {
                x0 = fmaxf(x0, 0.0f); x1 = fmaxf(x1, 0.0f);
                x2 = fmaxf(x2, 0.0f); x3 = fmaxf(x3, 0.0f);
            }
            if (v0r) *(uint32_t*)(outh + (size_t)row0 * HID + col) = h2pack(x0, x1);
            if (v1r) *(uint32_t*)(outh + (size_t)row1 * HID + col) = h2pack(x2, x3);
        }
    }
}

// ---------------------------------------------------------------------------
extern "C" void kernel_launch(void* const* d_in, const int* in_sizes, int n_in,
                              void* d_out, int out_size) {
    const float* x    = (const float*)d_in[0];
    const int*   ei   = (const int*)  d_in[1];
    const float* Wl0  = (const float*)d_in[2];
    const float* bl0  = (const float*)d_in[3];
    const float* Wr0  = (const float*)d_in[4];
    const float* Wl   = (const float*)d_in[5];
    const float* bl   = (const float*)d_in[6];
    const float* Wr   = (const float*)d_in[7];
    const float* bng  = (const float*)d_in[8];
    const float* bnb  = (const float*)d_in[9];
    const float* bnm  = (const float*)d_in[10];
    const float* bnv  = (const float*)d_in[11];
    const float* Wp0  = (const float*)d_in[12];
    const float* bp0  = (const float*)d_in[13];
    const float* Wp1  = (const float*)d_in[14];
    const float* bp1  = (const float*)d_in[15];
    const float* Wp2  = (const float*)d_in[16];
    const float* bp2  = (const float*)d_in[17];
    const float* pg   = (const float*)d_in[18];
    const float* pb   = (const float*)d_in[19];
    const float* pm   = (const float*)d_in[20];
    const float* pv   = (const float*)d_in[21];

    const int* src = ei;
    const int* dst = ei + EE;

    __half *agg16, *shA, *shB, *wl16, *wr16, *wp016, *wp116;
    float *agg10;
    int *deg, *inc, *rowptr, *cur, *csrc, *bsum;
    cudaGetSymbolAddress((void**)&agg16,  g_agg16);
    cudaGetSymbolAddress((void**)&shA,    g_shA);
    cudaGetSymbolAddress((void**)&shB,    g_shB);
    cudaGetSymbolAddress((void**)&agg10,  g_agg10);
    cudaGetSymbolAddress((void**)&wl16,   g_wl16);
    cudaGetSymbolAddress((void**)&wr16,   g_wr16);
    cudaGetSymbolAddress((void**)&wp016,  g_wp016);
    cudaGetSymbolAddress((void**)&wp116,  g_wp116);
    cudaGetSymbolAddress((void**)&deg,    g_deg);
    cudaGetSymbolAddress((void**)&inc,    g_inc);
    cudaGetSymbolAddress((void**)&rowptr, g_rowptr);
    cudaGetSymbolAddress((void**)&cur,    g_cur);
    cudaGetSymbolAddress((void**)&csrc,   g_csrc);
    cudaGetSymbolAddress((void**)&bsum,   g_bsum);

    // ---- weight conversion (fp32 -> fp16), once per call ----
    {
        int n4 = 4 * WMAT / 4;
        k_cvt4<<<(n4 + 255) / 256, 256>>>((const float4*)Wl, (uint2*)wl16, n4);
        k_cvt4<<<(n4 + 255) / 256, 256>>>((const float4*)Wr, (uint2*)wr16, n4);
        int p4 = WMAT / 4;
        k_cvt4<<<(p4 + 255) / 256, 256>>>((const float4*)Wp0, (uint2*)wp016, p4);
        k_cvt4<<<(p4 + 255) / 256, 256>>>((const float4*)Wp1, (uint2*)wp116, p4);
    }

    // ---- CSR build ----
    cudaMemsetAsync(deg, 0, NN * sizeof(int));
    k_hist<<<(EE + 255) / 256, 256>>>(dst, deg, EE);
    k_scan_block<<<NSCANB, SCAN_B>>>(deg, inc, bsum, NN);
    k_scan_bsum<<<1, 128>>>(bsum, NSCANB);
    k_csr_fin<<<(NN + 255) / 256, 256>>>(deg, inc, bsum, rowptr, cur, NN);
    k_fill<<<(EE + 255) / 256, 256>>>(src, dst, cur, csrc, EE);

    // ---- layer 0 (K=10) ----
    k_gather10<<<(NN * IN_DIM + 255) / 256, 256>>>(rowptr, csrc, x, agg10, NN);
    k_layer0<<<(NN + L0R - 1) / L0R, 384>>>(agg10, x, Wl0, bl0, Wr0,
                                            bng, bnb, bnm, bnv, shA, NN);

    // ---- layers 1..4: fp16 gather + dual fp16 mma GEMM ----
    const int gblocks = (NN + 63) / 64;
    for (int t = 1; t < TT; t++) {
        k_gather384<<<(NN * 32 + 255) / 256, 256>>>(rowptr, csrc, shA, agg16, NN);
        k_mma<<<gblocks, 512>>>(
            agg16, wl16 + (size_t)(t - 1) * WMAT, bl + (t - 1) * HID,
            shA,   wr16 + (size_t)(t - 1) * WMAT,
            bng + t * HID, bnb + t * HID, bnm + t * HID, bnv + t * HID,
            shB, nullptr, NN, 0, nullptr, nullptr);
        __half* ts = shA; shA = shB; shB = ts;
    }

    // ---- projection MLP (final [384->3] fused into second GEMM) ----
    k_mma<<<gblocks, 512>>>(shA, wp016, bp0, nullptr, nullptr,
                            pg, pb, pm, pv, shB, nullptr, NN, 1,
                            nullptr, nullptr);
    k_mma<<<gblocks, 512>>>(shB, wp116, bp1, nullptr, nullptr,
                            pg + HID, pb + HID, pm + HID, pv + HID,
                            nullptr, (float*)d_out, NN, 2,
                            Wp2, bp2);

    (void)in_sizes; (void)n_in; (void)out_size;
}

// round 11
// speedup vs baseline: 1.8509x; 1.0346x over previous
#include <cuda_runtime.h>
#include <cuda_fp16.h>
#include <math.h>
#include <cstdint>

#define NN 100000
#define EE 300000
#define IN_DIM 10
#define HID 384
#define TT 5
#define BN_EPS 1e-5f
#define WMAT (HID * HID)

#define SCAN_B 1024
#define NSCANB ((NN + SCAN_B - 1) / SCAN_B)   // 98

// Static scratch (allocation-free rule) — all activations fp16
__device__ __half  g_agg16[(size_t)NN * HID];
__device__ __half  g_shA [(size_t)NN * HID];
__device__ __half  g_shB [(size_t)NN * HID];
__device__ float   g_agg10[(size_t)NN * IN_DIM];
__device__ __half  g_wl16[4 * WMAT];
__device__ __half  g_wr16[4 * WMAT];
__device__ __half  g_wp016[WMAT];
__device__ __half  g_wp116[WMAT];
__device__ int   g_deg [NN];
__device__ int   g_inc [NN];
__device__ int   g_rowptr[NN + 1];
__device__ int   g_cur [NN];
__device__ int   g_csrc[EE];
__device__ int   g_bsum[128];

// ---------------------------------------------------------------------------
// helpers
// ---------------------------------------------------------------------------
__device__ __forceinline__ uint32_t smem_u32(const void* p) {
    uint32_t a;
    asm("{ .reg .u64 t; cvta.to.shared.u64 t, %1; cvt.u32.u64 %0, t; }" : "=r"(a) : "l"(p));
    return a;
}

__device__ __forceinline__ void mma_f16(float* c, uint32_t a0, uint32_t a1,
                                        uint32_t a2, uint32_t a3,
                                        uint32_t b0, uint32_t b1) {
    asm volatile("mma.sync.aligned.m16n8k16.row.col.f32.f16.f16.f32 "
                 "{%0,%1,%2,%3}, {%4,%5,%6,%7}, {%8,%9}, {%0,%1,%2,%3};"
                 : "+f"(c[0]), "+f"(c[1]), "+f"(c[2]), "+f"(c[3])
                 : "r"(a0), "r"(a1), "r"(a2), "r"(a3), "r"(b0), "r"(b1));
}

#define LDSM_X4(r0, r1, r2, r3, addr) \
    asm volatile("ldmatrix.sync.aligned.m8n8.x4.shared.b16 {%0,%1,%2,%3}, [%4];" \
                 : "=r"(r0), "=r"(r1), "=r"(r2), "=r"(r3) : "r"(addr))

__device__ __forceinline__ float elu_f(float v) {
    return (v > 0.0f) ? v : (__expf(v) - 1.0f);
}

__device__ __forceinline__ uint32_t h2pack(float x, float y) {
    __half2 h = __float22half2_rn(make_float2(x, y));
    return *(uint32_t*)&h;
}

// fp32 -> fp16 weight conversion (vectorized)
__global__ void k_cvt4(const float4* __restrict__ src, uint2* __restrict__ dst, int n4) {
    int i = blockIdx.x * blockDim.x + threadIdx.x;
    if (i >= n4) return;
    float4 v = src[i];
    uint2 o;
    o.x = h2pack(v.x, v.y);
    o.y = h2pack(v.z, v.w);
    dst[i] = o;
}

// ---------------------------------------------------------------------------
// CSR build
// ---------------------------------------------------------------------------
__global__ void k_hist(const int* __restrict__ dst, int* __restrict__ deg, int e) {
    int i = blockIdx.x * blockDim.x + threadIdx.x;
    if (i < e) atomicAdd(&deg[dst[i]], 1);
}

__global__ void k_scan_block(const int* __restrict__ deg, int* __restrict__ inc,
                             int* __restrict__ bsum, int n) {
    __shared__ int s[SCAN_B];
    int i = blockIdx.x * SCAN_B + threadIdx.x;
    s[threadIdx.x] = (i < n) ? deg[i] : 0;
    __syncthreads();
#pragma unroll
    for (int o = 1; o < SCAN_B; o <<= 1) {
        int t = (threadIdx.x >= o) ? s[threadIdx.x - o] : 0;
        __syncthreads();
        s[threadIdx.x] += t;
        __syncthreads();
    }
    if (i < n) inc[i] = s[threadIdx.x];
    if (threadIdx.x == SCAN_B - 1) bsum[blockIdx.x] = s[SCAN_B - 1];
}

__global__ void k_scan_bsum(int* __restrict__ bsum, int nb) {
    __shared__ int s[128];
    if (threadIdx.x < nb) s[threadIdx.x] = bsum[threadIdx.x];
    __syncthreads();
    if (threadIdx.x == 0) {
        int run = 0;
        for (int i = 0; i < nb; i++) { run += s[i]; s[i] = run; }
    }
    __syncthreads();
    if (threadIdx.x < nb) bsum[threadIdx.x] = s[threadIdx.x];
}

__global__ void k_csr_fin(const int* __restrict__ deg, const int* __restrict__ inc,
                          const int* __restrict__ bsum,
                          int* __restrict__ rowptr, int* __restrict__ cur, int n) {
    int i = blockIdx.x * blockDim.x + threadIdx.x;
    if (i >= n) return;
    int b = i / SCAN_B;
    int total = inc[i] + (b > 0 ? bsum[b - 1] : 0);
    rowptr[i + 1] = total;
    cur[i] = total - deg[i];
    if (i == 0) rowptr[0] = 0;
}

__global__ void k_fill(const int* __restrict__ src, const int* __restrict__ dst,
                       int* __restrict__ cur, int* __restrict__ csrc, int e) {
    int i = blockIdx.x * blockDim.x + threadIdx.x;
    if (i >= e) return;
    int pos = atomicAdd(&cur[dst[i]], 1);
    csrc[pos] = src[i];
}

// ---------------------------------------------------------------------------
// CSR mean-gather, width 384, fp16 in/out, fp32 accumulate, 2x unroll
// ---------------------------------------------------------------------------
__global__ void k_gather384(const int* __restrict__ rowptr, const int* __restrict__ csrc,
                            const __half* __restrict__ hs, __half* __restrict__ agg,
                            int n) {
    int node = (blockIdx.x * blockDim.x + threadIdx.x) >> 5;
    int lane = threadIdx.x & 31;
    if (node >= n) return;
    int beg = rowptr[node], end = rowptr[node + 1];
    float a[12], b[12];
#pragma unroll
    for (int i = 0; i < 12; i++) { a[i] = 0.0f; b[i] = 0.0f; }

    int e = beg;
    for (; e + 1 < end; e += 2) {
        int s0 = csrc[e], s1 = csrc[e + 1];
        const uint2* p0 = (const uint2*)(hs + (size_t)s0 * HID) + lane;
        const uint2* p1 = (const uint2*)(hs + (size_t)s1 * HID) + lane;
        uint2 u0 = p0[0], u1 = p0[32], u2 = p0[64];
        uint2 w0 = p1[0], w1 = p1[32], w2 = p1[64];
        float2 f;
        f = __half22float2(*(__half2*)&u0.x); a[0] += f.x; a[1] += f.y;
        f = __half22float2(*(__half2*)&u0.y); a[2] += f.x; a[3] += f.y;
        f = __half22float2(*(__half2*)&u1.x); a[4] += f.x; a[5] += f.y;
        f = __half22float2(*(__half2*)&u1.y); a[6] += f.x; a[7] += f.y;
        f = __half22float2(*(__half2*)&u2.x); a[8] += f.x; a[9] += f.y;
        f = __half22float2(*(__half2*)&u2.y); a[10] += f.x; a[11] += f.y;
        f = __half22float2(*(__half2*)&w0.x); b[0] += f.x; b[1] += f.y;
        f = __half22float2(*(__half2*)&w0.y); b[2] += f.x; b[3] += f.y;
        f = __half22float2(*(__half2*)&w1.x); b[4] += f.x; b[5] += f.y;
        f = __half22float2(*(__half2*)&w1.y); b[6] += f.x; b[7] += f.y;
        f = __half22float2(*(__half2*)&w2.x); b[8] += f.x; b[9] += f.y;
        f = __half22float2(*(__half2*)&w2.y); b[10] += f.x; b[11] += f.y;
    }
    if (e < end) {
        const uint2* p0 = (const uint2*)(hs + (size_t)csrc[e] * HID) + lane;
        uint2 u0 = p0[0], u1 = p0[32], u2 = p0[64];
        float2 f;
        f = __half22float2(*(__half2*)&u0.x); a[0] += f.x; a[1] += f.y;
        f = __half22float2(*(__half2*)&u0.y); a[2] += f.x; a[3] += f.y;
        f = __half22float2(*(__half2*)&u1.x); a[4] += f.x; a[5] += f.y;
        f = __half22float2(*(__half2*)&u1.y); a[6] += f.x; a[7] += f.y;
        f = __half22float2(*(__half2*)&u2.x); a[8] += f.x; a[9] += f.y;
        f = __half22float2(*(__half2*)&u2.y); a[10] += f.x; a[11] += f.y;
    }

    float iv = 1.0f / fmaxf((float)(end - beg), 1.0f);
    uint2* o = (uint2*)(agg + (size_t)node * HID) + lane;
    uint2 r;
    r.x = h2pack((a[0]+b[0])*iv, (a[1]+b[1])*iv);
    r.y = h2pack((a[2]+b[2])*iv, (a[3]+b[3])*iv);
    o[0] = r;
    r.x = h2pack((a[4]+b[4])*iv, (a[5]+b[5])*iv);
    r.y = h2pack((a[6]+b[6])*iv, (a[7]+b[7])*iv);
    o[32] = r;
    r.x = h2pack((a[8]+b[8])*iv, (a[9]+b[9])*iv);
    r.y = h2pack((a[10]+b[10])*iv, (a[11]+b[11])*iv);
    o[64] = r;
}

// width 10: thread per (node, feature), fp32 source
__global__ void k_gather10(const int* __restrict__ rowptr, const int* __restrict__ csrc,
                           const float* __restrict__ x, float* __restrict__ agg, int n) {
    int idx = blockIdx.x * blockDim.x + threadIdx.x;
    if (idx >= n * IN_DIM) return;
    int node = idx / IN_DIM, f = idx % IN_DIM;
    int beg = rowptr[node], end = rowptr[node + 1];
    float a = 0.0f;
    for (int e = beg; e < end; e++)
        a += x[(size_t)csrc[e] * IN_DIM + f];
    agg[idx] = a / fmaxf((float)(end - beg), 1.0f);
}

// ---------------------------------------------------------------------------
// Layer 0 SAGE: K=10, 32 rows/block, 384 threads; writes fp16 only
// ---------------------------------------------------------------------------
#define L0R 32
__global__ void k_layer0(const float* __restrict__ agg, const float* __restrict__ x,
                         const float* __restrict__ Wl, const float* __restrict__ bl,
                         const float* __restrict__ Wr,
                         const float* __restrict__ bng, const float* __restrict__ bnb,
                         const float* __restrict__ bnm, const float* __restrict__ bnv,
                         __half* __restrict__ hs, int n) {
    __shared__ float sA[L0R][IN_DIM];
    __shared__ float sX[L0R][IN_DIM];
    __shared__ float red[L0R];
    int t = threadIdx.x;
    int row0 = blockIdx.x * L0R;

    if (t < L0R * IN_DIM) {
        int r = t / IN_DIM, k = t % IN_DIM;
        int row = row0 + r;
        sA[r][k] = (row < n) ? agg[(size_t)row * IN_DIM + k] : 0.0f;
        sX[r][k] = (row < n) ? x[(size_t)row * IN_DIM + k] : 0.0f;
    } else if (t < L0R * IN_DIM + L0R) {
        red[t - L0R * IN_DIM] = 0.0f;
    }
    __syncthreads();

    int j = t;
    float wl[IN_DIM], wr[IN_DIM];
#pragma unroll
    for (int k = 0; k < IN_DIM; k++) {
        wl[k] = Wl[j * IN_DIM + k];
        wr[k] = Wr[j * IN_DIM + k];
    }
    float bb = bl[j];

    float v[L0R];
#pragma unroll
    for (int r = 0; r < L0R; r++) {
        float s = bb;
#pragma unroll
        for (int k = 0; k < IN_DIM; k++)
            s += sA[r][k] * wl[k] + sX[r][k] * wr[k];
        v[r] = s;
    }

    int lane = t & 31;
#pragma unroll
    for (int r = 0; r < L0R; r++) {
        float p = v[r] * v[r];
#pragma unroll
        for (int o = 16; o > 0; o >>= 1) p += __shfl_xor_sync(0xFFFFFFFFu, p, o);
        if (lane == 0) atomicAdd(&red[r], p);
    }
    __syncthreads();

    float gm = bng[j], gb = bnb[j], mm = bnm[j], vv = bnv[j];
    float bscale = rsqrtf(vv + BN_EPS) * gm;
#pragma unroll
    for (int r = 0; r < L0R; r++) {
        int row = row0 + r;
        if (row >= n) continue;
        float sc = 1.0f / fmaxf(sqrtf(red[r]), 1e-12f);
        float val = elu_f((v[r] * sc - mm) * bscale + gb);
        hs[(size_t)row * HID + j] = __float2half(val);
    }
}

// ---------------------------------------------------------------------------
// fp16 mma.sync m16n8k16 fused GEMM — double-buffered stages, 1 bar/iter,
// ldmatrix fragment loads. Proven HSTR=24 layout.
//   C[64, 384] = A1 * W1^T (+ A2 * W2^T) + bias   (A, W fp16)
//   epi 0: L2-normalize row, BN, ELU -> fp16 out
//   epi 1: BN, ReLU -> fp16 out
//   epi 2: BN, ReLU, then outf = h @ Wp2^T + bp2 (writes [N,3] fp32)
// ---------------------------------------------------------------------------
#define HSTR 24
#define ABUF (64 * HSTR)         // 1536 halves
#define WBUF (384 * HSTR)        // 9216 halves
#define DSMEM_HALVES (2 * ABUF + 2 * WBUF)   // 21504 halves = 43008 B
#define DSMEM_BYTES (DSMEM_HALVES * 2)

__global__ void __launch_bounds__(512, 1)
k_mma(const __half* __restrict__ A1, const __half* __restrict__ W1,
      const float* __restrict__ bias,
      const __half* __restrict__ A2, const __half* __restrict__ W2,
      const float* __restrict__ bng, const float* __restrict__ bnb,
      const float* __restrict__ bnm, const float* __restrict__ bnv,
      __half* __restrict__ outh, float* __restrict__ outf,
      int nrows, int epi,
      const float* __restrict__ Wp2, const float* __restrict__ bp2) {
    extern __shared__ __half smh[];
    __half* AsB0 = smh;
    __half* AsB1 = smh + ABUF;
    __half* WsB0 = smh + 2 * ABUF;
    __half* WsB1 = smh + 2 * ABUF + WBUF;

    __shared__ float sSB[HID], sS2[HID], sAD[HID];
    __shared__ float sWp[3 * HID];
    __shared__ float red[64];
    __shared__ float redF[192];

    const int tid  = threadIdx.x;
    const int lane = tid & 31;
    const int wid  = tid >> 5;
    const int rw   = wid & 1;
    const int cw   = wid >> 1;
    const int g    = lane >> 2;
    const int t4   = lane & 3;
    const int warpRow = rw * 32;
    const int cb   = cw * 48;
    const int rb   = blockIdx.x * 64;

    for (int c = tid; c < HID; c += 512) {
        float s2 = rsqrtf(bnv[c] + BN_EPS) * bng[c];
        sSB[c] = bias[c];
        sS2[c] = s2;
        sAD[c] = bnb[c] - bnm[c] * s2;
    }
    if (tid < 64) red[tid] = 0.0f;
    if (tid < 192) redF[tid] = 0.0f;
    if (epi == 2)
        for (int c = tid; c < 3 * HID; c += 512) sWp[c] = Wp2[c];

    // ldmatrix lane addresses per buffer (loop-invariant)
    const int m8 = lane >> 3;
    const int r8 = lane & 7;
    uint32_t aAddr[2][2], bAddr[2][3];
    {
        int rowi = (m8 & 1) * 8 + r8;
        int koff = (m8 >> 1) * 8;
        int nrowi = (m8 >> 1) * 8 + r8;
        int nkoff = (m8 & 1) * 8;
#pragma unroll
        for (int mt = 0; mt < 2; mt++) {
            int off = (warpRow + mt * 16 + rowi) * HSTR + koff;
            aAddr[0][mt] = smem_u32(&AsB0[off]);
            aAddr[1][mt] = smem_u32(&AsB1[off]);
        }
#pragma unroll
        for (int p = 0; p < 3; p++) {
            int off = (cb + p * 16 + nrowi) * HSTR + nkoff;
            bAddr[0][p] = smem_u32(&WsB0[off]);
            bAddr[1][p] = smem_u32(&WsB1[off]);
        }
    }

    const int ar = tid >> 2, aq = tid & 3;
    const int aOff = ar * HSTR + aq * 4;
    int wOff[3];
#pragma unroll
    for (int i = 0; i < 3; i++) {
        int idx = tid + i * 512;
        wOff[i] = (idx >> 2) * HSTR + (idx & 3) * 4;
    }
    int wr_[3], wq_[3];
#pragma unroll
    for (int i = 0; i < 3; i++) {
        int idx = tid + i * 512;
        wr_[i] = idx >> 2;
        wq_[i] = idx & 3;
    }

    const int npass = (A2 == nullptr) ? 1 : 2;
    const int S = 24 * npass;

    float acc[2][6][4];
#pragma unroll
    for (int mt = 0; mt < 2; mt++)
#pragma unroll
        for (int nt = 0; nt < 6; nt++)
#pragma unroll
            for (int q = 0; q < 4; q++) acc[mt][nt][q] = 0.0f;

    uint2 avP = make_uint2(0u, 0u);
    uint2 wvP[3];

    // prologue: fetch chunk 0 and stage into buffer 0
    {
        if (tid < 256) {
            int row = rb + ar;
            if (row < nrows)
                avP = *(const uint2*)(A1 + (size_t)row * HID + aq * 4);
        }
#pragma unroll
        for (int i = 0; i < 3; i++)
            wvP[i] = *(const uint2*)(W1 + (size_t)wr_[i] * HID + wq_[i] * 4);
        if (tid < 256)
            *(uint2*)&AsB0[aOff] = avP;
#pragma unroll
        for (int i = 0; i < 3; i++)
            *(uint2*)&WsB0[wOff[i]] = wvP[i];
    }

    for (int it = 0; it < S; it++) {
        const int b = it & 1;
        __syncthreads();   // stores to buf b (prev iter / prologue) now visible

        // prefetch chunk it+1 into regs (overlaps with compute below)
        if (it + 1 < S) {
            const int itn = it + 1;
            const int pass = itn / 24;
            const int k0 = (itn % 24) * 16;
            const __half* A = pass ? A2 : A1;
            const __half* W = pass ? W2 : W1;
            if (tid < 256) {
                int row = rb + ar;
                avP = make_uint2(0u, 0u);
                if (row < nrows)
                    avP = *(const uint2*)(A + (size_t)row * HID + k0 + aq * 4);
            }
#pragma unroll
            for (int i = 0; i < 3; i++)
                wvP[i] = *(const uint2*)(W + (size_t)wr_[i] * HID + k0 + wq_[i] * 4);
        }

        // compute from buffer b: 5x ldmatrix.x4 + 12 MMAs
        {
            uint32_t a[2][4];
            LDSM_X4(a[0][0], a[0][1], a[0][2], a[0][3], aAddr[b][0]);
            LDSM_X4(a[1][0], a[1][1], a[1][2], a[1][3], aAddr[b][1]);
            uint32_t bfr[12];
            LDSM_X4(bfr[0], bfr[1], bfr[2],  bfr[3],  bAddr[b][0]);
            LDSM_X4(bfr[4], bfr[5], bfr[6],  bfr[7],  bAddr[b][1]);
            LDSM_X4(bfr[8], bfr[9], bfr[10], bfr[11], bAddr[b][2]);
#pragma unroll
            for (int nt = 0; nt < 6; nt++) {
                uint32_t b0 = bfr[nt * 2], b1 = bfr[nt * 2 + 1];
                mma_f16(acc[0][nt], a[0][0], a[0][1], a[0][2], a[0][3], b0, b1);
                mma_f16(acc[1][nt], a[1][0], a[1][1], a[1][2], a[1][3], b0, b1);
            }
        }

        // stage chunk it+1 into the other buffer
        if (it + 1 < S) {
            __half* An = b ? AsB0 : AsB1;
            __half* Wn = b ? WsB0 : WsB1;
            if (tid < 256)
                *(uint2*)&An[aOff] = avP;
#pragma unroll
            for (int i = 0; i < 3; i++)
                *(uint2*)&Wn[wOff[i]] = wvP[i];
        }
    }
    __syncthreads();

    // ---- epilogue ----
#pragma unroll
    for (int nt = 0; nt < 6; nt++) {
        int col = cb + nt * 8 + 2 * t4;
        float b0 = sSB[col], b1 = sSB[col + 1];
#pragma unroll
        for (int mt = 0; mt < 2; mt++) {
            acc[mt][nt][0] += b0; acc[mt][nt][1] += b1;
            acc[mt][nt][2] += b0; acc[mt][nt][3] += b1;
        }
    }

    float sc0[2] = {1.0f, 1.0f}, sc1[2] = {1.0f, 1.0f};
    if (epi == 0) {
#pragma unroll
        for (int mt = 0; mt < 2; mt++) {
            float s0 = 0.0f, s1 = 0.0f;
#pragma unroll
            for (int nt = 0; nt < 6; nt++) {
                s0 = fmaf(acc[mt][nt][0], acc[mt][nt][0], s0);
                s0 = fmaf(acc[mt][nt][1], acc[mt][nt][1], s0);
                s1 = fmaf(acc[mt][nt][2], acc[mt][nt][2], s1);
                s1 = fmaf(acc[mt][nt][3], acc[mt][nt][3], s1);
            }
            s0 += __shfl_xor_sync(0xFFFFFFFFu, s0, 1);
            s0 += __shfl_xor_sync(0xFFFFFFFFu, s0, 2);
            s1 += __shfl_xor_sync(0xFFFFFFFFu, s1, 1);
            s1 += __shfl_xor_sync(0xFFFFFFFFu, s1, 2);
            if (t4 == 0) {
                atomicAdd(&red[warpRow + mt * 16 + g], s0);
                atomicAdd(&red[warpRow + mt * 16 + g + 8], s1);
            }
        }
        __syncthreads();
#pragma unroll
        for (int mt = 0; mt < 2; mt++) {
            sc0[mt] = 1.0f / fmaxf(sqrtf(red[warpRow + mt * 16 + g]), 1e-12f);
            sc1[mt] = 1.0f / fmaxf(sqrtf(red[warpRow + mt * 16 + g + 8]), 1e-12f);
        }
    }

    if (epi == 2) {
        float p0[2][3], p1[2][3];
#pragma unroll
        for (int mt = 0; mt < 2; mt++)
#pragma unroll
            for (int o = 0; o < 3; o++) { p0[mt][o] = 0.0f; p1[mt][o] = 0.0f; }

#pragma unroll
        for (int mt = 0; mt < 2; mt++) {
#pragma unroll
            for (int nt = 0; nt < 6; nt++) {
                int col = cb + nt * 8 + 2 * t4;
                float m0 = sS2[col], m1 = sS2[col + 1];
                float d0 = sAD[col], d1 = sAD[col + 1];
                float x0 = fmaxf(acc[mt][nt][0] * m0 + d0, 0.0f);
                float x1 = fmaxf(acc[mt][nt][1] * m1 + d1, 0.0f);
                float x2 = fmaxf(acc[mt][nt][2] * m0 + d0, 0.0f);
                float x3 = fmaxf(acc[mt][nt][3] * m1 + d1, 0.0f);
#pragma unroll
                for (int o = 0; o < 3; o++) {
                    float w0 = sWp[o * HID + col], w1 = sWp[o * HID + col + 1];
                    p0[mt][o] = fmaf(x0, w0, fmaf(x1, w1, p0[mt][o]));
                    p1[mt][o] = fmaf(x2, w0, fmaf(x3, w1, p1[mt][o]));
                }
            }
        }
#pragma unroll
        for (int mt = 0; mt < 2; mt++)
#pragma unroll
            for (int o = 0; o < 3; o++) {
                float v0 = p0[mt][o], v1 = p1[mt][o];
                v0 += __shfl_xor_sync(0xFFFFFFFFu, v0, 1);
                v0 += __shfl_xor_sync(0xFFFFFFFFu, v0, 2);
                v1 += __shfl_xor_sync(0xFFFFFFFFu, v1, 1);
                v1 += __shfl_xor_sync(0xFFFFFFFFu, v1, 2);
                if (t4 == 0) {
                    atomicAdd(&redF[(warpRow + mt * 16 + g) * 3 + o], v0);
                    atomicAdd(&redF[(warpRow + mt * 16 + g + 8) * 3 + o], v1);
                }
            }
        __syncthreads();
        if (tid < 64) {
            int row = rb + tid;
            if (row < nrows) {
                outf[(size_t)row * 3 + 0] = redF[tid * 3 + 0] + bp2[0];
                outf[(size_t)row * 3 + 1] = redF[tid * 3 + 1] + bp2[1];
                outf[(size_t)row * 3 + 2] = redF[tid * 3 + 2] + bp2[2];
            }
        }
        return;
    }

#pragma unroll
    for (int mt = 0; mt < 2; mt++) {
        int row0 = rb + warpRow + mt * 16 + g;
        int row1 = row0 + 8;
        bool v0r = (row0 < nrows), v1r = (row1 < nrows);
#pragma unroll
        for (int nt = 0; nt < 6; nt++) {
            int col = cb + nt * 8 + 2 * t4;
            float m0 = sS2[col], m1 = sS2[col + 1];
            float d0 = sAD[col], d1 = sAD[col + 1];
            float x0 = acc[mt][nt][0] * sc0[mt] * m0 + d0;
            float x1 = acc[mt][nt][1] * sc0[mt] * m1 + d1;
            float x2 = acc[mt][nt][2] * sc1[mt] * m0 + d0;
            float x3 = acc[mt][nt][3] * sc1[mt] * m1 + d1;
            if (epi == 0) {
                x0 = elu_f(x0); x1 = elu_f(x1);
                x2 = elu_f(x2); x3 = elu_f(x3);
            } else {
                x0 = fmaxf(x0, 0.0f); x1 = fmaxf(x1, 0.0f);
                x2 = fmaxf(x2, 0.0f); x3 = fmaxf(x3, 0.0f);
            }
            if (v0r) *(uint32_t*)(outh + (size_t)row0 * HID + col) = h2pack(x0, x1);
            if (v1r) *(uint32_t*)(outh + (size_t)row1 * HID + col) = h2pack(x2, x3);
        }
    }
}

// ---------------------------------------------------------------------------
extern "C" void kernel_launch(void* const* d_in, const int* in_sizes, int n_in,
                              void* d_out, int out_size) {
    const float* x    = (const float*)d_in[0];
    const int*   ei   = (const int*)  d_in[1];
    const float* Wl0  = (const float*)d_in[2];
    const float* bl0  = (const float*)d_in[3];
    const float* Wr0  = (const float*)d_in[4];
    const float* Wl   = (const float*)d_in[5];
    const float* bl   = (const float*)d_in[6];
    const float* Wr   = (const float*)d_in[7];
    const float* bng  = (const float*)d_in[8];
    const float* bnb  = (const float*)d_in[9];
    const float* bnm  = (const float*)d_in[10];
    const float* bnv  = (const float*)d_in[11];
    const float* Wp0  = (const float*)d_in[12];
    const float* bp0  = (const float*)d_in[13];
    const float* Wp1  = (const float*)d_in[14];
    const float* bp1  = (const float*)d_in[15];
    const float* Wp2  = (const float*)d_in[16];
    const float* bp2  = (const float*)d_in[17];
    const float* pg   = (const float*)d_in[18];
    const float* pb   = (const float*)d_in[19];
    const float* pm   = (const float*)d_in[20];
    const float* pv   = (const float*)d_in[21];

    const int* src = ei;
    const int* dst = ei + EE;

    __half *agg16, *shA, *shB, *wl16, *wr16, *wp016, *wp116;
    float *agg10;
    int *deg, *inc, *rowptr, *cur, *csrc, *bsum;
    cudaGetSymbolAddress((void**)&agg16,  g_agg16);
    cudaGetSymbolAddress((void**)&shA,    g_shA);
    cudaGetSymbolAddress((void**)&shB,    g_shB);
    cudaGetSymbolAddress((void**)&agg10,  g_agg10);
    cudaGetSymbolAddress((void**)&wl16,   g_wl16);
    cudaGetSymbolAddress((void**)&wr16,   g_wr16);
    cudaGetSymbolAddress((void**)&wp016,  g_wp016);
    cudaGetSymbolAddress((void**)&wp116,  g_wp116);
    cudaGetSymbolAddress((void**)&deg,    g_deg);
    cudaGetSymbolAddress((void**)&inc,    g_inc);
    cudaGetSymbolAddress((void**)&rowptr, g_rowptr);
    cudaGetSymbolAddress((void**)&cur,    g_cur);
    cudaGetSymbolAddress((void**)&csrc,   g_csrc);
    cudaGetSymbolAddress((void**)&bsum,   g_bsum);

    cudaFuncSetAttribute(k_mma, cudaFuncAttributeMaxDynamicSharedMemorySize, DSMEM_BYTES);

    // ---- weight conversion (fp32 -> fp16), once per call ----
    {
        int n4 = 4 * WMAT / 4;
        k_cvt4<<<(n4 + 255) / 256, 256>>>((const float4*)Wl, (uint2*)wl16, n4);
        k_cvt4<<<(n4 + 255) / 256, 256>>>((const float4*)Wr, (uint2*)wr16, n4);
        int p4 = WMAT / 4;
        k_cvt4<<<(p4 + 255) / 256, 256>>>((const float4*)Wp0, (uint2*)wp016, p4);
        k_cvt4<<<(p4 + 255) / 256, 256>>>((const float4*)Wp1, (uint2*)wp116, p4);
    }

    // ---- CSR build ----
    cudaMemsetAsync(deg, 0, NN * sizeof(int));
    k_hist<<<(EE + 255) / 256, 256>>>(dst, deg, EE);
    k_scan_block<<<NSCANB, SCAN_B>>>(deg, inc, bsum, NN);
    k_scan_bsum<<<1, 128>>>(bsum, NSCANB);
    k_csr_fin<<<(NN + 255) / 256, 256>>>(deg, inc, bsum, rowptr, cur, NN);
    k_fill<<<(EE + 255) / 256, 256>>>(src, dst, cur, csrc, EE);

    // ---- layer 0 (K=10) ----
    k_gather10<<<(NN * IN_DIM + 255) / 256, 256>>>(rowptr, csrc, x, agg10, NN);
    k_layer0<<<(NN + L0R - 1) / L0R, 384>>>(agg10, x, Wl0, bl0, Wr0,
                                            bng, bnb, bnm, bnv, shA, NN);

    // ---- layers 1..4: fp16 gather + dual fp16 mma GEMM ----
    const int gblocks = (NN + 63) / 64;
    for (int t = 1; t < TT; t++) {
        k_gather384<<<(NN * 32 + 255) / 256, 256>>>(rowptr, csrc, shA, agg16, NN);
        k_mma<<<gblocks, 512, DSMEM_BYTES>>>(
            agg16, wl16 + (size_t)(t - 1) * WMAT, bl + (t - 1) * HID,
            shA,   wr16 + (size_t)(t - 1) * WMAT,
            bng + t * HID, bnb + t * HID, bnm + t * HID, bnv + t * HID,
            shB, nullptr, NN, 0, nullptr, nullptr);
        __half* ts = shA; shA = shB; shB = ts;
    }

    // ---- projection MLP (final [384->3] fused into second GEMM) ----
    k_mma<<<gblocks, 512, DSMEM_BYTES>>>(shA, wp016, bp0, nullptr, nullptr,
                                         pg, pb, pm, pv, shB, nullptr, NN, 1,
                                         nullptr, nullptr);
    k_mma<<<gblocks, 512, DSMEM_BYTES>>>(shB, wp116, bp1, nullptr, nullptr,
                                         pg + HID, pb + HID, pm + HID, pv + HID,
                                         nullptr, (float*)d_out, NN, 2,
                                         Wp2, bp2);

    (void)in_sizes; (void)n_in; (void)out_size;
}